// round 2
// baseline (speedup 1.0000x reference)
#include <cuda_runtime.h>
#include <math.h>

// ---------------- problem constants ----------------
#define BB   2
#define TT   4096
#define HIDD 2048
#define HH   16
#define DD   128
#define MM   (BB*TT)          // 8192
#define NQKV (3*HIDD)         // 6144
#define CHK  64
#define NCK  (TT/CHK)         // 64
#define ETILE 32              // value-dim tile per GLA block

// ---------------- scratch (static device memory; no allocation) ----------------
__device__ float g_qkv[MM * NQKV];          // 8192 x 6144
__device__ float g_q  [BB*HH*TT*DD];        // (B,H,T,D)
__device__ float g_k  [BB*HH*TT*DD];
__device__ float g_v  [BB*HH*TT*DD];
__device__ float g_o  [MM * HIDD];          // (B,T,H*D)
__device__ float g_gate[MM * HIDD];         // gate, then reused as x after gate_norm

// =================================================================
// SGEMM (TN): C[M,N] = A[M,K] * B[N,K]^T   (both row-major, K-contiguous)
// BM=BN=128, BK=16, 256 threads, 8x8 per thread. All dims multiples.
// MODE 0: plain store. MODE 1: sigmoid epilogue.
// =================================================================
template<int MODE>
__global__ void __launch_bounds__(256)
sgemm_tn(const float* __restrict__ A, const float* __restrict__ Bw,
         float* __restrict__ C, int Mn, int Nn, int Kn)
{
    __shared__ float As[16][128];
    __shared__ float Bs[16][128];
    const int tid = threadIdx.x;
    const int tx = tid & 15, ty = tid >> 4;
    const int bm = blockIdx.y * 128, bn = blockIdx.x * 128;
    const float* Ap = A  + (size_t)bm * Kn;
    const float* Bp = Bw + (size_t)bn * Kn;

    float acc[8][8];
#pragma unroll
    for (int i = 0; i < 8; i++)
#pragma unroll
        for (int j = 0; j < 8; j++) acc[i][j] = 0.f;

    for (int k0 = 0; k0 < Kn; k0 += 16) {
#pragma unroll
        for (int it = 0; it < 2; it++) {
            int idx = tid * 2 + it;
            int row = idx >> 2;
            int col = (idx & 3) << 2;
            float4 a4 = *(const float4*)(Ap + (size_t)row * Kn + k0 + col);
            As[col  ][row] = a4.x;
            As[col+1][row] = a4.y;
            As[col+2][row] = a4.z;
            As[col+3][row] = a4.w;
            float4 b4 = *(const float4*)(Bp + (size_t)row * Kn + k0 + col);
            Bs[col  ][row] = b4.x;
            Bs[col+1][row] = b4.y;
            Bs[col+2][row] = b4.z;
            Bs[col+3][row] = b4.w;
        }
        __syncthreads();
#pragma unroll
        for (int kk = 0; kk < 16; kk++) {
            float af[8], bf[8];
            *(float4*)(af)     = *(const float4*)(&As[kk][ty*8]);
            *(float4*)(af + 4) = *(const float4*)(&As[kk][ty*8 + 4]);
            *(float4*)(bf)     = *(const float4*)(&Bs[kk][tx*8]);
            *(float4*)(bf + 4) = *(const float4*)(&Bs[kk][tx*8 + 4]);
#pragma unroll
            for (int i = 0; i < 8; i++)
#pragma unroll
                for (int j = 0; j < 8; j++)
                    acc[i][j] = fmaf(af[i], bf[j], acc[i][j]);
        }
        __syncthreads();
    }
#pragma unroll
    for (int i = 0; i < 8; i++) {
        float* cp = C + (size_t)(bm + ty*8 + i) * Nn + bn + tx*8;
#pragma unroll
        for (int j = 0; j < 8; j++) {
            float v = acc[i][j];
            if (MODE == 1) v = 1.f / (1.f + expf(-v));
            cp[j] = v;
        }
    }
}

// =================================================================
// Per-head RMSNorm + RoPE + transpose to (B,H,T,D).  q gets D^-0.5.
// One block = one (b,t,h); 128 threads = one d each.
// =================================================================
__global__ void __launch_bounds__(128)
norm_rope_kernel(const float* __restrict__ qw, const float* __restrict__ kw,
                 const int* __restrict__ pos)
{
    const int blk = blockIdx.x;
    const int bt = blk >> 4, h = blk & 15;
    const int b = bt >> 12, t = bt & 4095;
    const int d = threadIdx.x;
    __shared__ float buf[128];
    __shared__ float red[4];

    const float* base = g_qkv + (size_t)bt * NQKV + h * DD;
    const int p = pos[bt];

    float cth = 1.f, sth = 0.f;
    if (d < 64) {
        int i = d & 31;
        float freq = (float)p * powf(10000.f, -(float)(2 * i) / 64.f);
        cth = cosf(freq); sth = sinf(freq);
    }
    const size_t oidx = ((size_t)(b * HH + h) * TT + t) * DD + d;

    // ---- q ----
    {
        float v = base[d];
        float ss = v * v;
#pragma unroll
        for (int o = 16; o; o >>= 1) ss += __shfl_xor_sync(0xffffffffu, ss, o);
        if ((d & 31) == 0) red[d >> 5] = ss;
        __syncthreads();
        float rs = rsqrtf((red[0] + red[1] + red[2] + red[3]) * (1.f / 128.f) + 1e-6f);
        float nv = qw[d] * v * rs;
        buf[d] = nv;
        __syncthreads();
        float o = nv;
        if (d < 64) {
            float partner = (d < 32) ? -buf[d + 32] : buf[d - 32];
            o = nv * cth + partner * sth;
        }
        g_q[oidx] = o * 0.08838834764831845f;   // * D^-0.5
        __syncthreads();
    }
    // ---- k ----
    {
        float v = base[HIDD + d];
        float ss = v * v;
#pragma unroll
        for (int o = 16; o; o >>= 1) ss += __shfl_xor_sync(0xffffffffu, ss, o);
        if ((d & 31) == 0) red[d >> 5] = ss;
        __syncthreads();
        float rs = rsqrtf((red[0] + red[1] + red[2] + red[3]) * (1.f / 128.f) + 1e-6f);
        float nv = kw[d] * v * rs;
        buf[d] = nv;
        __syncthreads();
        float o = nv;
        if (d < 64) {
            float partner = (d < 32) ? -buf[d + 32] : buf[d - 32];
            o = nv * cth + partner * sth;
        }
        g_k[oidx] = o;
    }
    // ---- v passthrough ----
    g_v[oidx] = base[2 * HIDD + d];
}

// =================================================================
// Chunked simple-GLA scan. grid = (B*H, D/ETILE), 256 threads.
// Each block carries S[128][ETILE] in smem across 64 chunks.
// att (q@k^T) recomputed per e-tile (cheap vs. occupancy win).
// =================================================================
#define GLA_SMEM_FLOATS (64*129*2 + 64*33 + 64*65*2 + 128*33 + 128)

__global__ void __launch_bounds__(256)
gla_kernel()
{
    const int bh = blockIdx.x;
    const int b = bh >> 4, h = bh & 15;
    const int e0 = blockIdx.y * ETILE;
    extern __shared__ float sm[];
    float* qs   = sm;                // 64 x (stride 129)
    float* ks   = qs  + 64 * 129;
    float* vs   = ks  + 64 * 129;    // 64 x (stride 33)
    float* at   = vs  + 64 * 33;     // 64 x (stride 65)
    float* msk  = at  + 64 * 65;     // 64 x (stride 65)
    float* Ssm  = msk + 64 * 65;     // 128 x (stride 33)
    float* qdec = Ssm + 128 * 33;    // 64
    float* kdec = qdec + 64;         // 64
    const int tid = threadIdx.x;

    const float g = (float)(-exp2(-0.5 * (double)(h + 1)) * (1.0 - 11.0 / 31.0 + 1e-5));
    const float chdec = expf(g * 64.f);

    for (int i = tid; i < 64 * 64; i += 256) {
        int c = i >> 6, e = i & 63;
        msk[c * 65 + e] = (c >= e) ? expf(g * (float)(c - e)) : 0.f;
    }
    if (tid < 64) {
        qdec[tid] = expf(g * (float)(tid + 1));
        kdec[tid] = expf(g * (float)(63 - tid));
    }
    for (int i = tid; i < 128 * ETILE; i += 256) {
        int d = i >> 5, e = i & 31;
        Ssm[d * 33 + e] = 0.f;
    }
    const float* qg = g_q + (size_t)bh * TT * DD;
    const float* kg = g_k + (size_t)bh * TT * DD;
    const float* vg = g_v + (size_t)bh * TT * DD;
    __syncthreads();

    for (int ch = 0; ch < NCK; ch++) {
        const float* qrow = qg + (size_t)ch * CHK * DD;
        const float* krow = kg + (size_t)ch * CHK * DD;
        const float* vrow = vg + (size_t)ch * CHK * DD;
#pragma unroll
        for (int it = 0; it < 8; it++) {
            int i = tid + it * 256;
            int r = i >> 5, c4 = (i & 31) << 2;
            float4 v4 = *(const float4*)(qrow + r * DD + c4);
            float* d1 = qs + r * 129 + c4;
            d1[0] = v4.x; d1[1] = v4.y; d1[2] = v4.z; d1[3] = v4.w;
            v4 = *(const float4*)(krow + r * DD + c4);
            d1 = ks + r * 129 + c4;
            d1[0] = v4.x; d1[1] = v4.y; d1[2] = v4.z; d1[3] = v4.w;
        }
#pragma unroll
        for (int it = 0; it < 2; it++) {
            int i = tid + it * 256;
            int r = i >> 3, c4 = (i & 7) << 2;
            float4 v4 = *(const float4*)(vrow + r * DD + e0 + c4);
            float* d1 = vs + r * 33 + c4;
            d1[0] = v4.x; d1[1] = v4.y; d1[2] = v4.z; d1[3] = v4.w;
        }
        __syncthreads();

        // ---- att = (q @ k^T) * mask, 4x4 per thread ----
        {
            const int c0 = (tid >> 4) << 2, E0 = (tid & 15) << 2;
            float a4[4][4];
#pragma unroll
            for (int i = 0; i < 4; i++)
#pragma unroll
                for (int j = 0; j < 4; j++) a4[i][j] = 0.f;
            for (int d = 0; d < DD; d++) {
                float qv[4], kv[4];
#pragma unroll
                for (int i = 0; i < 4; i++) qv[i] = qs[(c0 + i) * 129 + d];
#pragma unroll
                for (int j = 0; j < 4; j++) kv[j] = ks[(E0 + j) * 129 + d];
#pragma unroll
                for (int i = 0; i < 4; i++)
#pragma unroll
                    for (int j = 0; j < 4; j++)
                        a4[i][j] = fmaf(qv[i], kv[j], a4[i][j]);
            }
#pragma unroll
            for (int i = 0; i < 4; i++)
#pragma unroll
                for (int j = 0; j < 4; j++)
                    at[(c0 + i) * 65 + E0 + j] = a4[i][j] * msk[(c0 + i) * 65 + E0 + j];
        }
        __syncthreads();

        // ---- o = att @ v + qdec * (q @ S), 2x4 per thread; write gmem ----
        {
            const int c0 = (tid >> 3) << 1, el = (tid & 7) << 2;
            float o4[2][4];
            float s4[2][4];
#pragma unroll
            for (int i = 0; i < 2; i++)
#pragma unroll
                for (int j = 0; j < 4; j++) { o4[i][j] = 0.f; s4[i][j] = 0.f; }
            for (int e2 = 0; e2 < 64; e2++) {
                float av0 = at[c0 * 65 + e2];
                float av1 = at[(c0 + 1) * 65 + e2];
                float vv[4];
#pragma unroll
                for (int j = 0; j < 4; j++) vv[j] = vs[e2 * 33 + el + j];
#pragma unroll
                for (int j = 0; j < 4; j++) {
                    o4[0][j] = fmaf(av0, vv[j], o4[0][j]);
                    o4[1][j] = fmaf(av1, vv[j], o4[1][j]);
                }
            }
            for (int d = 0; d < DD; d++) {
                float q0 = qs[c0 * 129 + d];
                float q1 = qs[(c0 + 1) * 129 + d];
                float sv[4];
#pragma unroll
                for (int j = 0; j < 4; j++) sv[j] = Ssm[d * 33 + el + j];
#pragma unroll
                for (int j = 0; j < 4; j++) {
                    s4[0][j] = fmaf(q0, sv[j], s4[0][j]);
                    s4[1][j] = fmaf(q1, sv[j], s4[1][j]);
                }
            }
#pragma unroll
            for (int i = 0; i < 2; i++) {
                const float qd = qdec[c0 + i];
                float* op = g_o + ((size_t)(b * TT + ch * CHK + c0 + i)) * HIDD
                                + h * DD + e0 + el;
#pragma unroll
                for (int j = 0; j < 4; j++)
                    op[j] = o4[i][j] + qd * s4[i][j];
            }
        }
        __syncthreads();

        // ---- S = chdec*S + (k*kdec)^T @ v, 4x4 per thread ----
        {
            const int d0 = (tid >> 3) << 2, el = (tid & 7) << 2;
            float su[4][4];
#pragma unroll
            for (int i = 0; i < 4; i++)
#pragma unroll
                for (int j = 0; j < 4; j++) su[i][j] = 0.f;
            for (int c = 0; c < 64; c++) {
                float kd = kdec[c];
                float kv[4], vv[4];
#pragma unroll
                for (int i = 0; i < 4; i++) kv[i] = ks[c * 129 + d0 + i] * kd;
#pragma unroll
                for (int j = 0; j < 4; j++) vv[j] = vs[c * 33 + el + j];
#pragma unroll
                for (int i = 0; i < 4; i++)
#pragma unroll
                    for (int j = 0; j < 4; j++)
                        su[i][j] = fmaf(kv[i], vv[j], su[i][j]);
            }
#pragma unroll
            for (int i = 0; i < 4; i++)
#pragma unroll
                for (int j = 0; j < 4; j++) {
                    float* sp = &Ssm[(d0 + i) * 33 + el + j];
                    *sp = chdec * (*sp) + su[i][j];
                }
        }
        __syncthreads();
    }
}

// =================================================================
// group RMSNorm(o) * g_norm_w * gate -> overwrite g_gate (becomes x)
// =================================================================
__global__ void __launch_bounds__(128)
gate_norm_kernel(const float* __restrict__ gnw)
{
    const int blk = blockIdx.x;
    const int bt = blk >> 4, h = blk & 15;
    const int d = threadIdx.x;
    __shared__ float red[4];
    const size_t idx = (size_t)bt * HIDD + h * DD + d;
    float v = g_o[idx];
    float ss = v * v;
#pragma unroll
    for (int o = 16; o; o >>= 1) ss += __shfl_xor_sync(0xffffffffu, ss, o);
    if ((d & 31) == 0) red[d >> 5] = ss;
    __syncthreads();
    float rs = rsqrtf((red[0] + red[1] + red[2] + red[3]) * (1.f / 128.f) + 1e-6f);
    float gate = g_gate[idx];
    g_gate[idx] = gnw[h * DD + d] * v * rs * gate;
}

// =================================================================
// launch
// =================================================================
extern "C" void kernel_launch(void* const* d_in, const int* in_sizes, int n_in,
                              void* d_out, int out_size)
{
    const float* hidden   = (const float*)d_in[0];
    const float* w_qkv    = (const float*)d_in[1];
    const float* q_ln_w   = (const float*)d_in[2];
    const float* k_ln_w   = (const float*)d_in[3];
    const float* g_norm_w = (const float*)d_in[4];
    const float* w_gproj  = (const float*)d_in[5];
    const float* w_dense  = (const float*)d_in[6];
    const int*   pos      = (const int*)d_in[7];
    float* out = (float*)d_out;

    void *pqkv, *pgate;
    cudaGetSymbolAddress(&pqkv, g_qkv);
    cudaGetSymbolAddress(&pgate, g_gate);

    const int gla_smem = GLA_SMEM_FLOATS * 4;
    cudaFuncSetAttribute(gla_kernel, cudaFuncAttributeMaxDynamicSharedMemorySize, gla_smem);

    // 1) qkv = hidden @ w_qkv^T
    sgemm_tn<0><<<dim3(NQKV / 128, MM / 128), 256>>>(hidden, w_qkv, (float*)pqkv, MM, NQKV, HIDD);
    // 2) per-head rmsnorm + rope + layout (B,H,T,D)
    norm_rope_kernel<<<MM * HH, 128>>>(q_ln_w, k_ln_w, pos);
    // 3) chunked GLA scan -> g_o (B,T,H*D)
    gla_kernel<<<dim3(BB * HH, DD / ETILE), 256, gla_smem>>>();
    // 4) gate = sigmoid(hidden @ w_gproj^T)
    sgemm_tn<1><<<dim3(HIDD / 128, MM / 128), 256>>>(hidden, w_gproj, (float*)pgate, MM, HIDD, HIDD);
    // 5) x = groupnorm(o) * w * gate   (in place into g_gate)
    gate_norm_kernel<<<MM * HH, 128>>>(g_norm_w);
    // 6) out = x @ w_dense^T
    sgemm_tn<0><<<dim3(HIDD / 128, MM / 128), 256>>>((const float*)pgate, w_dense, out, MM, HIDD, HIDD);
}

// round 5
// speedup vs baseline: 2.2900x; 2.2900x over previous
#include <cuda_runtime.h>
#include <cuda_bf16.h>
#include <math.h>
#include <stdint.h>

// ---------------- problem constants ----------------
#define BB   2
#define TT   4096
#define HIDD 2048
#define HH   16
#define DD   128
#define MM   (BB*TT)          // 8192
#define NQKV (3*HIDD)         // 6144
#define CHK  64
#define NCK  (TT/CHK)         // 64
#define ETILE 32

// ---------------- GEMM tiling (HMMA mma.sync path) ----------------
#define GBM 128
#define GBN 128
#define GBK 32
#define NKI (HIDD/GBK)            // 64
#define TPAD 40                   // padded row stride in halfs (80B, conflict-free)
#define TILE_B (GBM*TPAD*2)       // 10240 bytes per operand tile
#define OFF_AH 0
#define OFF_AL (1*TILE_B)
#define OFF_BH (2*TILE_B)
#define OFF_BL (3*TILE_B)
#define STAGE_B (4*TILE_B)        // 40960
#define NSTAGE 3
#define GEMM_DYN (NSTAGE*STAGE_B) // 122880

// ---------------- scratch (static device memory) ----------------
__device__ float g_qkv [(size_t)MM*NQKV];
__device__ float g_q   [(size_t)BB*HH*TT*DD];
__device__ float g_k   [(size_t)BB*HH*TT*DD];
__device__ float g_v   [(size_t)BB*HH*TT*DD];
__device__ float g_o   [(size_t)MM*HIDD];
__device__ float g_gate[(size_t)MM*HIDD];
__device__ __nv_bfloat16 g_ah [(size_t)MM*HIDD];
__device__ __nv_bfloat16 g_al [(size_t)MM*HIDD];
__device__ __nv_bfloat16 g_wqh[(size_t)NQKV*HIDD];
__device__ __nv_bfloat16 g_wql[(size_t)NQKV*HIDD];
__device__ __nv_bfloat16 g_wgh[(size_t)HIDD*HIDD];
__device__ __nv_bfloat16 g_wgl[(size_t)HIDD*HIDD];
__device__ __nv_bfloat16 g_wdh[(size_t)HIDD*HIDD];
__device__ __nv_bfloat16 g_wdl[(size_t)HIDD*HIDD];

// ---------------- ptx helpers ----------------
__device__ __forceinline__ uint32_t s2u(const void* p) {
    uint32_t a;
    asm("{ .reg .u64 t; cvta.to.shared.u64 t, %1; cvt.u32.u64 %0, t; }"
        : "=r"(a) : "l"(p));
    return a;
}
__device__ __forceinline__ void cpa16(uint32_t dst, const void* src) {
    asm volatile("cp.async.cg.shared.global [%0], [%1], 16;" :: "r"(dst), "l"(src));
}
#define CP_COMMIT() asm volatile("cp.async.commit_group;" ::: "memory")
#define CP_WAIT1()  asm volatile("cp.async.wait_group 1;" ::: "memory")

__device__ __forceinline__ void ldsm4(uint32_t (&r)[4], uint32_t addr) {
    asm volatile("ldmatrix.sync.aligned.m8n8.x4.shared.b16 {%0,%1,%2,%3}, [%4];"
        : "=r"(r[0]), "=r"(r[1]), "=r"(r[2]), "=r"(r[3]) : "r"(addr));
}
__device__ __forceinline__ void mma16816(float (&d)[4], const uint32_t (&a)[4],
                                         uint32_t b0, uint32_t b1) {
    asm volatile(
        "mma.sync.aligned.m16n8k16.row.col.f32.bf16.bf16.f32 "
        "{%0,%1,%2,%3}, {%4,%5,%6,%7}, {%8,%9}, {%0,%1,%2,%3};"
        : "+f"(d[0]), "+f"(d[1]), "+f"(d[2]), "+f"(d[3])
        : "r"(a[0]), "r"(a[1]), "r"(a[2]), "r"(a[3]), "r"(b0), "r"(b1));
}

// =================================================================
// split fp32 -> (bf16 hi, bf16 lo)
// =================================================================
__global__ void __launch_bounds__(256)
cvt_split(const float* __restrict__ x, __nv_bfloat16* __restrict__ hi,
          __nv_bfloat16* __restrict__ lo, int n4)
{
    int i = blockIdx.x * 256 + threadIdx.x;
    if (i >= n4) return;
    float4 v = ((const float4*)x)[i];
    __nv_bfloat16 h0 = __float2bfloat16_rn(v.x);
    __nv_bfloat16 h1 = __float2bfloat16_rn(v.y);
    __nv_bfloat16 h2 = __float2bfloat16_rn(v.z);
    __nv_bfloat16 h3 = __float2bfloat16_rn(v.w);
    __nv_bfloat16 l0 = __float2bfloat16_rn(v.x - __bfloat162float(h0));
    __nv_bfloat16 l1 = __float2bfloat16_rn(v.y - __bfloat162float(h1));
    __nv_bfloat16 l2 = __float2bfloat16_rn(v.z - __bfloat162float(h2));
    __nv_bfloat16 l3 = __float2bfloat16_rn(v.w - __bfloat162float(h3));
    ((__nv_bfloat162*)hi)[2*i]   = __nv_bfloat162(h0, h1);
    ((__nv_bfloat162*)hi)[2*i+1] = __nv_bfloat162(h2, h3);
    ((__nv_bfloat162*)lo)[2*i]   = __nv_bfloat162(l0, l1);
    ((__nv_bfloat162*)lo)[2*i+1] = __nv_bfloat162(l2, l3);
}

// =================================================================
// bf16x3 GEMM via mma.sync (TN): C[M,N] = (Ah+Al)[M,K] @ ((Bh+Bl)[N,K])^T
// BM=BN=128, BK=32, 8 warps (2x4), 64x32 warp tile, 3-stage cp.async.
// MODE 0: plain store. MODE 1: sigmoid epilogue.
// =================================================================
template<int MODE>
__global__ void __launch_bounds__(256)
gemm_bf16x3(const __nv_bfloat16* __restrict__ Ah, const __nv_bfloat16* __restrict__ Al,
            const __nv_bfloat16* __restrict__ Bh, const __nv_bfloat16* __restrict__ Bl,
            float* __restrict__ C, int Nn)
{
    extern __shared__ char dyn[];
    const uint32_t sb = s2u(dyn);
    const int tid = threadIdx.x;
    const int warp = tid >> 5, lane = tid & 31;
    const int wm = warp >> 2, wn = warp & 3;
    const int bm = blockIdx.y * GBM, bn = blockIdx.x * GBN;

    const __nv_bfloat16* apH = Ah + (size_t)bm * HIDD;
    const __nv_bfloat16* apL = Al + (size_t)bm * HIDD;
    const __nv_bfloat16* bpH = Bh + (size_t)bn * HIDD;
    const __nv_bfloat16* bpL = Bl + (size_t)bn * HIDD;

    float acc[4][4][4];
#pragma unroll
    for (int mi = 0; mi < 4; mi++)
#pragma unroll
        for (int ni = 0; ni < 4; ni++)
#pragma unroll
            for (int r = 0; r < 4; r++) acc[mi][ni][r] = 0.f;

    // ldmatrix per-lane base offsets (in halfs)
    const int a_row = wm * 64 + (lane & 7) + ((lane >> 3) & 1) * 8;
    const int a_koff = (lane >> 4) * 8;
    const int b_row = wn * 32 + (lane & 7) + ((lane >> 4) & 1) * 8;
    const int b_koff = ((lane >> 3) & 1) * 8;

    auto fill = [&](int s, int k0) {
        const uint32_t base = sb + s * STAGE_B;
#pragma unroll
        for (int it = 0; it < 2; it++) {
            const int idx = tid + it * 256;          // 0..511
            const int row = idx >> 2;
            const int ch = idx & 3;
            const uint32_t d = (uint32_t)(row * (TPAD * 2) + ch * 16);
            const size_t gsrc = (size_t)row * HIDD + k0 + ch * 8;
            cpa16(base + OFF_AH + d, apH + gsrc);
            cpa16(base + OFF_AL + d, apL + gsrc);
            cpa16(base + OFF_BH + d, bpH + gsrc);
            cpa16(base + OFF_BL + d, bpL + gsrc);
        }
    };

    fill(0, 0);            CP_COMMIT();
    fill(1, GBK);          CP_COMMIT();

    for (int i = 0; i < NKI; i++) {
        const int s = i % NSTAGE;
        CP_WAIT1();
        __syncthreads();

        const uint32_t st = sb + s * STAGE_B;
#pragma unroll
        for (int ks = 0; ks < 2; ks++) {
            uint32_t ah[4][4], al[4][4], bb[2][4];
#pragma unroll
            for (int mi = 0; mi < 4; mi++) {
                const uint32_t ao = (uint32_t)(((a_row + mi * 16) * TPAD + ks * 16 + a_koff) * 2);
                ldsm4(ah[mi], st + OFF_AH + ao);
                ldsm4(al[mi], st + OFF_AL + ao);
            }
#pragma unroll
            for (int nb = 0; nb < 2; nb++) {
                const uint32_t bo = (uint32_t)(((b_row + nb * 16) * TPAD + ks * 16 + b_koff) * 2);
                ldsm4(bb[nb], st + OFF_BH + bo);
            }
#pragma unroll
            for (int mi = 0; mi < 4; mi++)
#pragma unroll
                for (int ni = 0; ni < 4; ni++) {
                    mma16816(acc[mi][ni], ah[mi], bb[ni >> 1][(ni & 1) * 2], bb[ni >> 1][(ni & 1) * 2 + 1]);
                }
#pragma unroll
            for (int mi = 0; mi < 4; mi++)
#pragma unroll
                for (int ni = 0; ni < 4; ni++) {
                    mma16816(acc[mi][ni], al[mi], bb[ni >> 1][(ni & 1) * 2], bb[ni >> 1][(ni & 1) * 2 + 1]);
                }
#pragma unroll
            for (int nb = 0; nb < 2; nb++) {
                const uint32_t bo = (uint32_t)(((b_row + nb * 16) * TPAD + ks * 16 + b_koff) * 2);
                ldsm4(bb[nb], st + OFF_BL + bo);
            }
#pragma unroll
            for (int mi = 0; mi < 4; mi++)
#pragma unroll
                for (int ni = 0; ni < 4; ni++) {
                    mma16816(acc[mi][ni], ah[mi], bb[ni >> 1][(ni & 1) * 2], bb[ni >> 1][(ni & 1) * 2 + 1]);
                }
        }
        __syncthreads();
        if (i + 2 < NKI) fill((i + 2) % NSTAGE, (i + 2) * GBK);
        CP_COMMIT();
    }

    // epilogue
    const int r0 = bm + wm * 64 + (lane >> 2);
    const int c0 = bn + wn * 32 + (lane & 3) * 2;
#pragma unroll
    for (int mi = 0; mi < 4; mi++) {
#pragma unroll
        for (int ni = 0; ni < 4; ni++) {
            float2 v0 = make_float2(acc[mi][ni][0], acc[mi][ni][1]);
            float2 v1 = make_float2(acc[mi][ni][2], acc[mi][ni][3]);
            if (MODE == 1) {
                v0.x = 1.f / (1.f + expf(-v0.x));
                v0.y = 1.f / (1.f + expf(-v0.y));
                v1.x = 1.f / (1.f + expf(-v1.x));
                v1.y = 1.f / (1.f + expf(-v1.y));
            }
            *(float2*)(C + (size_t)(r0 + mi * 16) * Nn + c0 + ni * 8) = v0;
            *(float2*)(C + (size_t)(r0 + mi * 16 + 8) * Nn + c0 + ni * 8) = v1;
        }
    }
}

// =================================================================
// Per-head RMSNorm + RoPE + transpose to (B,H,T,D).  q gets D^-0.5.
// =================================================================
__global__ void __launch_bounds__(128)
norm_rope_kernel(const float* __restrict__ qw, const float* __restrict__ kw,
                 const int* __restrict__ pos)
{
    const int blk = blockIdx.x;
    const int bt = blk >> 4, h = blk & 15;
    const int b = bt >> 12, t = bt & 4095;
    const int d = threadIdx.x;
    __shared__ float buf[128];
    __shared__ float red[4];

    const float* base = g_qkv + (size_t)bt * NQKV + h * DD;
    const int p = pos[bt];

    float cth = 1.f, sth = 0.f;
    if (d < 64) {
        int i = d & 31;
        float freq = (float)p * powf(10000.f, -(float)(2 * i) / 64.f);
        cth = cosf(freq); sth = sinf(freq);
    }
    const size_t oidx = ((size_t)(b * HH + h) * TT + t) * DD + d;

    {
        float v = base[d];
        float ss = v * v;
#pragma unroll
        for (int o = 16; o; o >>= 1) ss += __shfl_xor_sync(0xffffffffu, ss, o);
        if ((d & 31) == 0) red[d >> 5] = ss;
        __syncthreads();
        float rs = rsqrtf((red[0] + red[1] + red[2] + red[3]) * (1.f / 128.f) + 1e-6f);
        float nv = qw[d] * v * rs;
        buf[d] = nv;
        __syncthreads();
        float o = nv;
        if (d < 64) {
            float partner = (d < 32) ? -buf[d + 32] : buf[d - 32];
            o = nv * cth + partner * sth;
        }
        g_q[oidx] = o * 0.08838834764831845f;
        __syncthreads();
    }
    {
        float v = base[HIDD + d];
        float ss = v * v;
#pragma unroll
        for (int o = 16; o; o >>= 1) ss += __shfl_xor_sync(0xffffffffu, ss, o);
        if ((d & 31) == 0) red[d >> 5] = ss;
        __syncthreads();
        float rs = rsqrtf((red[0] + red[1] + red[2] + red[3]) * (1.f / 128.f) + 1e-6f);
        float nv = kw[d] * v * rs;
        buf[d] = nv;
        __syncthreads();
        float o = nv;
        if (d < 64) {
            float partner = (d < 32) ? -buf[d + 32] : buf[d - 32];
            o = nv * cth + partner * sth;
        }
        g_k[oidx] = o;
    }
    g_v[oidx] = base[2 * HIDD + d];
}

// =================================================================
// Chunked simple-GLA scan (unchanged — known correct)
// =================================================================
#define GLA_SMEM_FLOATS (64*129*2 + 64*33 + 64*65*2 + 128*33 + 128)

__global__ void __launch_bounds__(256)
gla_kernel()
{
    const int bh = blockIdx.x;
    const int b = bh >> 4, h = bh & 15;
    const int e0 = blockIdx.y * ETILE;
    extern __shared__ float sm[];
    float* qs   = sm;
    float* ks   = qs  + 64 * 129;
    float* vs   = ks  + 64 * 129;
    float* at   = vs  + 64 * 33;
    float* msk  = at  + 64 * 65;
    float* Ssm  = msk + 64 * 65;
    float* qdec = Ssm + 128 * 33;
    float* kdec = qdec + 64;
    const int tid = threadIdx.x;

    const float g = (float)(-exp2(-0.5 * (double)(h + 1)) * (1.0 - 11.0 / 31.0 + 1e-5));
    const float chdec = expf(g * 64.f);

    for (int i = tid; i < 64 * 64; i += 256) {
        int c = i >> 6, e = i & 63;
        msk[c * 65 + e] = (c >= e) ? expf(g * (float)(c - e)) : 0.f;
    }
    if (tid < 64) {
        qdec[tid] = expf(g * (float)(tid + 1));
        kdec[tid] = expf(g * (float)(63 - tid));
    }
    for (int i = tid; i < 128 * ETILE; i += 256) {
        int d = i >> 5, e = i & 31;
        Ssm[d * 33 + e] = 0.f;
    }
    const float* qg = g_q + (size_t)bh * TT * DD;
    const float* kg = g_k + (size_t)bh * TT * DD;
    const float* vg = g_v + (size_t)bh * TT * DD;
    __syncthreads();

    for (int ch = 0; ch < NCK; ch++) {
        const float* qrow = qg + (size_t)ch * CHK * DD;
        const float* krow = kg + (size_t)ch * CHK * DD;
        const float* vrow = vg + (size_t)ch * CHK * DD;
#pragma unroll
        for (int it = 0; it < 8; it++) {
            int i = tid + it * 256;
            int r = i >> 5, c4 = (i & 31) << 2;
            float4 v4 = *(const float4*)(qrow + r * DD + c4);
            float* d1 = qs + r * 129 + c4;
            d1[0] = v4.x; d1[1] = v4.y; d1[2] = v4.z; d1[3] = v4.w;
            v4 = *(const float4*)(krow + r * DD + c4);
            d1 = ks + r * 129 + c4;
            d1[0] = v4.x; d1[1] = v4.y; d1[2] = v4.z; d1[3] = v4.w;
        }
#pragma unroll
        for (int it = 0; it < 2; it++) {
            int i = tid + it * 256;
            int r = i >> 3, c4 = (i & 7) << 2;
            float4 v4 = *(const float4*)(vrow + r * DD + e0 + c4);
            float* d1 = vs + r * 33 + c4;
            d1[0] = v4.x; d1[1] = v4.y; d1[2] = v4.z; d1[3] = v4.w;
        }
        __syncthreads();

        {
            const int c0 = (tid >> 4) << 2, E0 = (tid & 15) << 2;
            float a4[4][4];
#pragma unroll
            for (int i = 0; i < 4; i++)
#pragma unroll
                for (int j = 0; j < 4; j++) a4[i][j] = 0.f;
            for (int d = 0; d < DD; d++) {
                float qv[4], kv[4];
#pragma unroll
                for (int i = 0; i < 4; i++) qv[i] = qs[(c0 + i) * 129 + d];
#pragma unroll
                for (int j = 0; j < 4; j++) kv[j] = ks[(E0 + j) * 129 + d];
#pragma unroll
                for (int i = 0; i < 4; i++)
#pragma unroll
                    for (int j = 0; j < 4; j++)
                        a4[i][j] = fmaf(qv[i], kv[j], a4[i][j]);
            }
#pragma unroll
            for (int i = 0; i < 4; i++)
#pragma unroll
                for (int j = 0; j < 4; j++)
                    at[(c0 + i) * 65 + E0 + j] = a4[i][j] * msk[(c0 + i) * 65 + E0 + j];
        }
        __syncthreads();

        {
            const int c0 = (tid >> 3) << 1, el = (tid & 7) << 2;
            float o4[2][4];
            float s4[2][4];
#pragma unroll
            for (int i = 0; i < 2; i++)
#pragma unroll
                for (int j = 0; j < 4; j++) { o4[i][j] = 0.f; s4[i][j] = 0.f; }
            for (int e2 = 0; e2 < 64; e2++) {
                float av0 = at[c0 * 65 + e2];
                float av1 = at[(c0 + 1) * 65 + e2];
                float vv[4];
#pragma unroll
                for (int j = 0; j < 4; j++) vv[j] = vs[e2 * 33 + el + j];
#pragma unroll
                for (int j = 0; j < 4; j++) {
                    o4[0][j] = fmaf(av0, vv[j], o4[0][j]);
                    o4[1][j] = fmaf(av1, vv[j], o4[1][j]);
                }
            }
            for (int d = 0; d < DD; d++) {
                float q0 = qs[c0 * 129 + d];
                float q1 = qs[(c0 + 1) * 129 + d];
                float sv[4];
#pragma unroll
                for (int j = 0; j < 4; j++) sv[j] = Ssm[d * 33 + el + j];
#pragma unroll
                for (int j = 0; j < 4; j++) {
                    s4[0][j] = fmaf(q0, sv[j], s4[0][j]);
                    s4[1][j] = fmaf(q1, sv[j], s4[1][j]);
                }
            }
#pragma unroll
            for (int i = 0; i < 2; i++) {
                const float qd = qdec[c0 + i];
                float* op = g_o + ((size_t)(b * TT + ch * CHK + c0 + i)) * HIDD
                                + h * DD + e0 + el;
#pragma unroll
                for (int j = 0; j < 4; j++)
                    op[j] = o4[i][j] + qd * s4[i][j];
            }
        }
        __syncthreads();

        {
            const int d0 = (tid >> 3) << 2, el = (tid & 7) << 2;
            float su[4][4];
#pragma unroll
            for (int i = 0; i < 4; i++)
#pragma unroll
                for (int j = 0; j < 4; j++) su[i][j] = 0.f;
            for (int c = 0; c < 64; c++) {
                float kd = kdec[c];
                float kv[4], vv[4];
#pragma unroll
                for (int i = 0; i < 4; i++) kv[i] = ks[c * 129 + d0 + i] * kd;
#pragma unroll
                for (int j = 0; j < 4; j++) vv[j] = vs[c * 33 + el + j];
#pragma unroll
                for (int i = 0; i < 4; i++)
#pragma unroll
                    for (int j = 0; j < 4; j++)
                        su[i][j] = fmaf(kv[i], vv[j], su[i][j]);
            }
#pragma unroll
            for (int i = 0; i < 4; i++)
#pragma unroll
                for (int j = 0; j < 4; j++) {
                    float* sp = &Ssm[(d0 + i) * 33 + el + j];
                    *sp = chdec * (*sp) + su[i][j];
                }
        }
        __syncthreads();
    }
}

// =================================================================
// group RMSNorm(o) * g_norm_w * gate -> overwrite g_gate
// =================================================================
__global__ void __launch_bounds__(128)
gate_norm_kernel(const float* __restrict__ gnw)
{
    const int blk = blockIdx.x;
    const int bt = blk >> 4, h = blk & 15;
    const int d = threadIdx.x;
    __shared__ float red[4];
    const size_t idx = (size_t)bt * HIDD + h * DD + d;
    float v = g_o[idx];
    float ss = v * v;
#pragma unroll
    for (int o = 16; o; o >>= 1) ss += __shfl_xor_sync(0xffffffffu, ss, o);
    if ((d & 31) == 0) red[d >> 5] = ss;
    __syncthreads();
    float rs = rsqrtf((red[0] + red[1] + red[2] + red[3]) * (1.f / 128.f) + 1e-6f);
    float gate = g_gate[idx];
    g_gate[idx] = gnw[h * DD + d] * v * rs * gate;
}

// =================================================================
// launch
// =================================================================
extern "C" void kernel_launch(void* const* d_in, const int* in_sizes, int n_in,
                              void* d_out, int out_size)
{
    const float* hidden   = (const float*)d_in[0];
    const float* w_qkv    = (const float*)d_in[1];
    const float* q_ln_w   = (const float*)d_in[2];
    const float* k_ln_w   = (const float*)d_in[3];
    const float* g_norm_w = (const float*)d_in[4];
    const float* w_gproj  = (const float*)d_in[5];
    const float* w_dense  = (const float*)d_in[6];
    const int*   pos      = (const int*)d_in[7];
    float* out = (float*)d_out;

    void *pqkv, *pgate, *pah, *pal, *pwqh, *pwql, *pwgh, *pwgl, *pwdh, *pwdl;
    cudaGetSymbolAddress(&pqkv, g_qkv);
    cudaGetSymbolAddress(&pgate, g_gate);
    cudaGetSymbolAddress(&pah, g_ah);
    cudaGetSymbolAddress(&pal, g_al);
    cudaGetSymbolAddress(&pwqh, g_wqh);
    cudaGetSymbolAddress(&pwql, g_wql);
    cudaGetSymbolAddress(&pwgh, g_wgh);
    cudaGetSymbolAddress(&pwgl, g_wgl);
    cudaGetSymbolAddress(&pwdh, g_wdh);
    cudaGetSymbolAddress(&pwdl, g_wdl);

    const int gla_smem = GLA_SMEM_FLOATS * 4;
    cudaFuncSetAttribute(gla_kernel, cudaFuncAttributeMaxDynamicSharedMemorySize, gla_smem);
    cudaFuncSetAttribute(gemm_bf16x3<0>, cudaFuncAttributeMaxDynamicSharedMemorySize, GEMM_DYN);
    cudaFuncSetAttribute(gemm_bf16x3<1>, cudaFuncAttributeMaxDynamicSharedMemorySize, GEMM_DYN);

    // 0) bf16 hi/lo conversions
    cvt_split<<<(MM*HIDD/4 + 255)/256, 256>>>(hidden, (__nv_bfloat16*)pah, (__nv_bfloat16*)pal, MM*HIDD/4);
    cvt_split<<<(NQKV*HIDD/4 + 255)/256, 256>>>(w_qkv, (__nv_bfloat16*)pwqh, (__nv_bfloat16*)pwql, NQKV*HIDD/4);
    cvt_split<<<(HIDD*HIDD/4 + 255)/256, 256>>>(w_gproj, (__nv_bfloat16*)pwgh, (__nv_bfloat16*)pwgl, HIDD*HIDD/4);
    cvt_split<<<(HIDD*HIDD/4 + 255)/256, 256>>>(w_dense, (__nv_bfloat16*)pwdh, (__nv_bfloat16*)pwdl, HIDD*HIDD/4);

    // 1) qkv = hidden @ w_qkv^T
    gemm_bf16x3<0><<<dim3(NQKV/GBN, MM/GBM), 256, GEMM_DYN>>>(
        (const __nv_bfloat16*)pah, (const __nv_bfloat16*)pal,
        (const __nv_bfloat16*)pwqh, (const __nv_bfloat16*)pwql,
        (float*)pqkv, NQKV);
    // 2) gate = sigmoid(hidden @ w_gproj^T)
    gemm_bf16x3<1><<<dim3(HIDD/GBN, MM/GBM), 256, GEMM_DYN>>>(
        (const __nv_bfloat16*)pah, (const __nv_bfloat16*)pal,
        (const __nv_bfloat16*)pwgh, (const __nv_bfloat16*)pwgl,
        (float*)pgate, HIDD);
    // 3) per-head rmsnorm + rope + layout (B,H,T,D)
    norm_rope_kernel<<<MM * HH, 128>>>(q_ln_w, k_ln_w, pos);
    // 4) chunked GLA scan -> g_o
    gla_kernel<<<dim3(BB * HH, DD / ETILE), 256, gla_smem>>>();
    // 5) x = groupnorm(o) * w * gate
    gate_norm_kernel<<<MM * HH, 128>>>(g_norm_w);
    // 6) convert x -> bf16 hi/lo (reuse A buffers)
    cvt_split<<<(MM*HIDD/4 + 255)/256, 256>>>((const float*)pgate,
        (__nv_bfloat16*)pah, (__nv_bfloat16*)pal, MM*HIDD/4);
    // 7) out = x @ w_dense^T
    gemm_bf16x3<0><<<dim3(HIDD/GBN, MM/GBM), 256, GEMM_DYN>>>(
        (const __nv_bfloat16*)pah, (const __nv_bfloat16*)pal,
        (const __nv_bfloat16*)pwdh, (const __nv_bfloat16*)pwdl,
        out, HIDD);
}

// round 6
// speedup vs baseline: 2.6330x; 1.1498x over previous
#include <cuda_runtime.h>
#include <cuda_bf16.h>
#include <math.h>
#include <stdint.h>

// ---------------- problem constants ----------------
#define BB   2
#define TT   4096
#define HIDD 2048
#define HH   16
#define DD   128
#define MM   (BB*TT)          // 8192
#define NQKV (3*HIDD)         // 6144
#define CHK  64
#define NCK  (TT/CHK)         // 64

// ---------------- GEMM tiling (HMMA mma.sync path) ----------------
#define GBM 128
#define GBN 128
#define GBK 32
#define NKI (HIDD/GBK)            // 64
#define TPAD 40                   // padded row stride in halfs
#define TILE_B (GBM*TPAD*2)       // 10240 bytes per operand tile
#define OFF_AH 0
#define OFF_AL (1*TILE_B)
#define OFF_BH (2*TILE_B)
#define OFF_BL (3*TILE_B)
#define STAGE_B (4*TILE_B)        // 40960
#define NSTAGE 3
#define GEMM_DYN (NSTAGE*STAGE_B) // 122880

// ---------------- GLA tiling ----------------
#define SA   136                  // q/k/v tile stride (halfs)
#define SATT 72                   // att tile stride
#define SV   40                   // v e-tile stride (scan kernel)
#define GLAA_HALFS (6*64*SA + 2*64*SATT)              // 61440
#define GLAA_DYN   (GLAA_HALFS*2)                     // 122880
#define GLAS_HALFS (4*64*SA + 2*64*SV + 2*32*SA)      // 48640
#define GLAS_DYN   (GLAS_HALFS*2)                     // 97280

// ---------------- scratch (static device memory) ----------------
__device__ float g_qkv [(size_t)MM*NQKV];
__device__ float g_q   [(size_t)BB*HH*TT*DD];
__device__ float g_k   [(size_t)BB*HH*TT*DD];
__device__ float g_v   [(size_t)BB*HH*TT*DD];
__device__ float g_o   [(size_t)MM*HIDD];
__device__ float g_gate[(size_t)MM*HIDD];
__device__ __nv_bfloat16 g_ah [(size_t)MM*HIDD];
__device__ __nv_bfloat16 g_al [(size_t)MM*HIDD];
__device__ __nv_bfloat16 g_wqh[(size_t)NQKV*HIDD];
__device__ __nv_bfloat16 g_wql[(size_t)NQKV*HIDD];
__device__ __nv_bfloat16 g_wgh[(size_t)HIDD*HIDD];
__device__ __nv_bfloat16 g_wgl[(size_t)HIDD*HIDD];
__device__ __nv_bfloat16 g_wdh[(size_t)HIDD*HIDD];
__device__ __nv_bfloat16 g_wdl[(size_t)HIDD*HIDD];

// ---------------- ptx helpers ----------------
__device__ __forceinline__ uint32_t s2u(const void* p) {
    uint32_t a;
    asm("{ .reg .u64 t; cvta.to.shared.u64 t, %1; cvt.u32.u64 %0, t; }"
        : "=r"(a) : "l"(p));
    return a;
}
__device__ __forceinline__ void cpa16(uint32_t dst, const void* src) {
    asm volatile("cp.async.cg.shared.global [%0], [%1], 16;" :: "r"(dst), "l"(src));
}
#define CP_COMMIT() asm volatile("cp.async.commit_group;" ::: "memory")
#define CP_WAIT1()  asm volatile("cp.async.wait_group 1;" ::: "memory")
#define CP_WAIT0()  asm volatile("cp.async.wait_group 0;" ::: "memory")

__device__ __forceinline__ void ldsm4(uint32_t (&r)[4], uint32_t addr) {
    asm volatile("ldmatrix.sync.aligned.m8n8.x4.shared.b16 {%0,%1,%2,%3}, [%4];"
        : "=r"(r[0]), "=r"(r[1]), "=r"(r[2]), "=r"(r[3]) : "r"(addr));
}
__device__ __forceinline__ void ldsm4t(uint32_t (&r)[4], uint32_t addr) {
    asm volatile("ldmatrix.sync.aligned.m8n8.x4.trans.shared.b16 {%0,%1,%2,%3}, [%4];"
        : "=r"(r[0]), "=r"(r[1]), "=r"(r[2]), "=r"(r[3]) : "r"(addr));
}
__device__ __forceinline__ void mma16816(float (&d)[4], const uint32_t (&a)[4],
                                         uint32_t b0, uint32_t b1) {
    asm volatile(
        "mma.sync.aligned.m16n8k16.row.col.f32.bf16.bf16.f32 "
        "{%0,%1,%2,%3}, {%4,%5,%6,%7}, {%8,%9}, {%0,%1,%2,%3};"
        : "+f"(d[0]), "+f"(d[1]), "+f"(d[2]), "+f"(d[3])
        : "r"(a[0]), "r"(a[1]), "r"(a[2]), "r"(a[3]), "r"(b0), "r"(b1));
}

__device__ __forceinline__ void split1(float v, __nv_bfloat16& h, __nv_bfloat16& l) {
    h = __float2bfloat16_rn(v);
    l = __float2bfloat16_rn(v - __bfloat162float(h));
}
// store float4 as hi/lo bf16 pairs at half-offset off (even)
__device__ __forceinline__ void cvt4(__nv_bfloat16* H, __nv_bfloat16* L, int off, float4 v) {
    __nv_bfloat16 h0,l0,h1,l1,h2,l2,h3,l3;
    split1(v.x,h0,l0); split1(v.y,h1,l1); split1(v.z,h2,l2); split1(v.w,h3,l3);
    *(__nv_bfloat162*)(H+off)   = __nv_bfloat162(h0,h1);
    *(__nv_bfloat162*)(H+off+2) = __nv_bfloat162(h2,h3);
    *(__nv_bfloat162*)(L+off)   = __nv_bfloat162(l0,l1);
    *(__nv_bfloat162*)(L+off+2) = __nv_bfloat162(l2,l3);
}

// =================================================================
// split fp32 -> (bf16 hi, bf16 lo)
// =================================================================
__global__ void __launch_bounds__(256)
cvt_split(const float* __restrict__ x, __nv_bfloat16* __restrict__ hi,
          __nv_bfloat16* __restrict__ lo, int n4)
{
    int i = blockIdx.x * 256 + threadIdx.x;
    if (i >= n4) return;
    float4 v = ((const float4*)x)[i];
    __nv_bfloat16 h0,l0,h1,l1,h2,l2,h3,l3;
    split1(v.x,h0,l0); split1(v.y,h1,l1); split1(v.z,h2,l2); split1(v.w,h3,l3);
    ((__nv_bfloat162*)hi)[2*i]   = __nv_bfloat162(h0, h1);
    ((__nv_bfloat162*)hi)[2*i+1] = __nv_bfloat162(h2, h3);
    ((__nv_bfloat162*)lo)[2*i]   = __nv_bfloat162(l0, l1);
    ((__nv_bfloat162*)lo)[2*i+1] = __nv_bfloat162(l2, l3);
}

// =================================================================
// bf16x3 GEMM via mma.sync (TN) — unchanged from R5 (known good)
// =================================================================
template<int MODE>
__global__ void __launch_bounds__(256)
gemm_bf16x3(const __nv_bfloat16* __restrict__ Ah, const __nv_bfloat16* __restrict__ Al,
            const __nv_bfloat16* __restrict__ Bh, const __nv_bfloat16* __restrict__ Bl,
            float* __restrict__ C, int Nn)
{
    extern __shared__ char dyn[];
    const uint32_t sb = s2u(dyn);
    const int tid = threadIdx.x;
    const int warp = tid >> 5, lane = tid & 31;
    const int wm = warp >> 2, wn = warp & 3;
    const int bm = blockIdx.y * GBM, bn = blockIdx.x * GBN;

    const __nv_bfloat16* apH = Ah + (size_t)bm * HIDD;
    const __nv_bfloat16* apL = Al + (size_t)bm * HIDD;
    const __nv_bfloat16* bpH = Bh + (size_t)bn * HIDD;
    const __nv_bfloat16* bpL = Bl + (size_t)bn * HIDD;

    float acc[4][4][4];
#pragma unroll
    for (int mi = 0; mi < 4; mi++)
#pragma unroll
        for (int ni = 0; ni < 4; ni++)
#pragma unroll
            for (int r = 0; r < 4; r++) acc[mi][ni][r] = 0.f;

    const int a_row = wm * 64 + (lane & 7) + ((lane >> 3) & 1) * 8;
    const int a_koff = (lane >> 4) * 8;
    const int b_row = wn * 32 + (lane & 7) + ((lane >> 4) & 1) * 8;
    const int b_koff = ((lane >> 3) & 1) * 8;

    auto fill = [&](int s, int k0) {
        const uint32_t base = sb + s * STAGE_B;
#pragma unroll
        for (int it = 0; it < 2; it++) {
            const int idx = tid + it * 256;
            const int row = idx >> 2;
            const int ch = idx & 3;
            const uint32_t d = (uint32_t)(row * (TPAD * 2) + ch * 16);
            const size_t gsrc = (size_t)row * HIDD + k0 + ch * 8;
            cpa16(base + OFF_AH + d, apH + gsrc);
            cpa16(base + OFF_AL + d, apL + gsrc);
            cpa16(base + OFF_BH + d, bpH + gsrc);
            cpa16(base + OFF_BL + d, bpL + gsrc);
        }
    };

    fill(0, 0);            CP_COMMIT();
    fill(1, GBK);          CP_COMMIT();

    for (int i = 0; i < NKI; i++) {
        const int s = i % NSTAGE;
        CP_WAIT1();
        __syncthreads();

        const uint32_t st = sb + s * STAGE_B;
#pragma unroll
        for (int ks = 0; ks < 2; ks++) {
            uint32_t ah[4][4], al[4][4], bb[2][4];
#pragma unroll
            for (int mi = 0; mi < 4; mi++) {
                const uint32_t ao = (uint32_t)(((a_row + mi * 16) * TPAD + ks * 16 + a_koff) * 2);
                ldsm4(ah[mi], st + OFF_AH + ao);
                ldsm4(al[mi], st + OFF_AL + ao);
            }
#pragma unroll
            for (int nb = 0; nb < 2; nb++) {
                const uint32_t bo = (uint32_t)(((b_row + nb * 16) * TPAD + ks * 16 + b_koff) * 2);
                ldsm4(bb[nb], st + OFF_BH + bo);
            }
#pragma unroll
            for (int mi = 0; mi < 4; mi++)
#pragma unroll
                for (int ni = 0; ni < 4; ni++)
                    mma16816(acc[mi][ni], ah[mi], bb[ni >> 1][(ni & 1) * 2], bb[ni >> 1][(ni & 1) * 2 + 1]);
#pragma unroll
            for (int mi = 0; mi < 4; mi++)
#pragma unroll
                for (int ni = 0; ni < 4; ni++)
                    mma16816(acc[mi][ni], al[mi], bb[ni >> 1][(ni & 1) * 2], bb[ni >> 1][(ni & 1) * 2 + 1]);
#pragma unroll
            for (int nb = 0; nb < 2; nb++) {
                const uint32_t bo = (uint32_t)(((b_row + nb * 16) * TPAD + ks * 16 + b_koff) * 2);
                ldsm4(bb[nb], st + OFF_BL + bo);
            }
#pragma unroll
            for (int mi = 0; mi < 4; mi++)
#pragma unroll
                for (int ni = 0; ni < 4; ni++)
                    mma16816(acc[mi][ni], ah[mi], bb[ni >> 1][(ni & 1) * 2], bb[ni >> 1][(ni & 1) * 2 + 1]);
        }
        __syncthreads();
        if (i + 2 < NKI) fill((i + 2) % NSTAGE, (i + 2) * GBK);
        CP_COMMIT();
    }

    const int r0 = bm + wm * 64 + (lane >> 2);
    const int c0 = bn + wn * 32 + (lane & 3) * 2;
#pragma unroll
    for (int mi = 0; mi < 4; mi++) {
#pragma unroll
        for (int ni = 0; ni < 4; ni++) {
            float2 v0 = make_float2(acc[mi][ni][0], acc[mi][ni][1]);
            float2 v1 = make_float2(acc[mi][ni][2], acc[mi][ni][3]);
            if (MODE == 1) {
                v0.x = 1.f / (1.f + expf(-v0.x));
                v0.y = 1.f / (1.f + expf(-v0.y));
                v1.x = 1.f / (1.f + expf(-v1.x));
                v1.y = 1.f / (1.f + expf(-v1.y));
            }
            *(float2*)(C + (size_t)(r0 + mi * 16) * Nn + c0 + ni * 8) = v0;
            *(float2*)(C + (size_t)(r0 + mi * 16 + 8) * Nn + c0 + ni * 8) = v1;
        }
    }
}

// =================================================================
// Per-head RMSNorm + RoPE + transpose to (B,H,T,D) — unchanged
// =================================================================
__global__ void __launch_bounds__(128)
norm_rope_kernel(const float* __restrict__ qw, const float* __restrict__ kw,
                 const int* __restrict__ pos)
{
    const int blk = blockIdx.x;
    const int bt = blk >> 4, h = blk & 15;
    const int b = bt >> 12, t = bt & 4095;
    const int d = threadIdx.x;
    __shared__ float buf[128];
    __shared__ float red[4];

    const float* base = g_qkv + (size_t)bt * NQKV + h * DD;
    const int p = pos[bt];

    float cth = 1.f, sth = 0.f;
    if (d < 64) {
        int i = d & 31;
        float freq = (float)p * powf(10000.f, -(float)(2 * i) / 64.f);
        cth = cosf(freq); sth = sinf(freq);
    }
    const size_t oidx = ((size_t)(b * HH + h) * TT + t) * DD + d;

    {
        float v = base[d];
        float ss = v * v;
#pragma unroll
        for (int o = 16; o; o >>= 1) ss += __shfl_xor_sync(0xffffffffu, ss, o);
        if ((d & 31) == 0) red[d >> 5] = ss;
        __syncthreads();
        float rs = rsqrtf((red[0] + red[1] + red[2] + red[3]) * (1.f / 128.f) + 1e-6f);
        float nv = qw[d] * v * rs;
        buf[d] = nv;
        __syncthreads();
        float o = nv;
        if (d < 64) {
            float partner = (d < 32) ? -buf[d + 32] : buf[d - 32];
            o = nv * cth + partner * sth;
        }
        g_q[oidx] = o * 0.08838834764831845f;
        __syncthreads();
    }
    {
        float v = base[HIDD + d];
        float ss = v * v;
#pragma unroll
        for (int o = 16; o; o >>= 1) ss += __shfl_xor_sync(0xffffffffu, ss, o);
        if ((d & 31) == 0) red[d >> 5] = ss;
        __syncthreads();
        float rs = rsqrtf((red[0] + red[1] + red[2] + red[3]) * (1.f / 128.f) + 1e-6f);
        float nv = kw[d] * v * rs;
        buf[d] = nv;
        __syncthreads();
        float o = nv;
        if (d < 64) {
            float partner = (d < 32) ? -buf[d + 32] : buf[d - 32];
            o = nv * cth + partner * sth;
        }
        g_k[oidx] = o;
    }
    g_v[oidx] = base[2 * HIDD + d];
}

// =================================================================
// GLA kernel A (parallel): att = (q@k^T)*mask ; o_intra = att@v
// grid (NCK, B*H), 256 threads. bf16x3 mma throughout.
// =================================================================
__global__ void __launch_bounds__(256)
gla_intra()
{
    extern __shared__ __nv_bfloat16 smA[];
    __nv_bfloat16 *qh = smA,           *ql = qh + 64*SA,
                  *kh = ql + 64*SA,    *kl = kh + 64*SA,
                  *vh = kl + 64*SA,    *vl = vh + 64*SA,
                  *ath = vl + 64*SA,   *atl = ath + 64*SATT;
    const int tid = threadIdx.x, warp = tid >> 5, lane = tid & 31;
    const int ch = blockIdx.x, bh = blockIdx.y, b = bh >> 4, h = bh & 15;
    const float g = -exp2f(-0.5f * (float)(h + 1)) * (1.0f - 11.0f/31.0f + 1e-5f);

    const float* qg = g_q + ((size_t)bh * TT + ch * CHK) * DD;
    const float* kg = g_k + ((size_t)bh * TT + ch * CHK) * DD;
    const float* vg = g_v + ((size_t)bh * TT + ch * CHK) * DD;

    const uint32_t uqh = s2u(qh), uql = s2u(ql), ukh = s2u(kh), ukl = s2u(kl);
    const uint32_t uvh = s2u(vh), uvl = s2u(vl), uath = s2u(ath), uatl = s2u(atl);

    // v fp32 staged into (vh..vl) region via cp.async (32KB <= 34816B)
    const uint32_t uvst = uvh;
    float* vst = (float*)vh;
#pragma unroll
    for (int it = 0; it < 8; it++) {
        int idx = tid + it * 256;
        cpa16(uvst + idx * 16, vg + idx * 4);
    }
    CP_COMMIT();

    // q,k fp32 -> hi/lo bf16 smem
#pragma unroll
    for (int it = 0; it < 8; it++) {
        int idx = tid + it * 256;
        int r = idx >> 5, c = (idx & 31) << 2;
        cvt4(qh, ql, r * SA + c, *(const float4*)(qg + r * DD + c));
        cvt4(kh, kl, r * SA + c, *(const float4*)(kg + r * DD + c));
    }
    __syncthreads();

    // ---- att mma: M=64 N=64 K=128, warps 2x4 (tile 32x16) ----
    const int wm = warp >> 2, wn = warp & 3;
    {
        float acc[2][2][4];
#pragma unroll
        for (int mi = 0; mi < 2; mi++)
#pragma unroll
            for (int ni = 0; ni < 2; ni++)
#pragma unroll
                for (int r = 0; r < 4; r++) acc[mi][ni][r] = 0.f;

        const int arow = wm * 32 + (lane & 15);
        const int akoff = (lane >> 4) * 8;
        const int brow = wn * 16 + (lane & 7) + ((lane >> 4) & 1) * 8;
        const int bkoff = ((lane >> 3) & 1) * 8;
#pragma unroll
        for (int kk = 0; kk < 8; kk++) {
            uint32_t ahh[2][4], all[2][4], bhf[4], blf[4];
#pragma unroll
            for (int mi = 0; mi < 2; mi++) {
                uint32_t ao = (uint32_t)(((arow + mi*16) * SA + kk*16 + akoff) * 2);
                ldsm4(ahh[mi], uqh + ao);
                ldsm4(all[mi], uql + ao);
            }
            uint32_t bo = (uint32_t)((brow * SA + kk*16 + bkoff) * 2);
            ldsm4(bhf, ukh + bo);
            ldsm4(blf, ukl + bo);
#pragma unroll
            for (int mi = 0; mi < 2; mi++)
#pragma unroll
                for (int ni = 0; ni < 2; ni++) {
                    mma16816(acc[mi][ni], ahh[mi], bhf[ni*2], bhf[ni*2+1]);
                    mma16816(acc[mi][ni], ahh[mi], blf[ni*2], blf[ni*2+1]);
                    mma16816(acc[mi][ni], all[mi], bhf[ni*2], bhf[ni*2+1]);
                }
        }
        // mask + split-store att
#pragma unroll
        for (int mi = 0; mi < 2; mi++)
#pragma unroll
            for (int ni = 0; ni < 2; ni++)
#pragma unroll
                for (int half = 0; half < 2; half++) {
                    int row = wm*32 + mi*16 + (lane >> 2) + half*8;
                    int col = wn*16 + ni*8 + (lane & 3)*2;
                    float v0 = acc[mi][ni][half*2+0];
                    float v1 = acc[mi][ni][half*2+1];
                    v0 = (row >= col)     ? v0 * expf(g * (float)(row - col))     : 0.f;
                    v1 = (row >= col + 1) ? v1 * expf(g * (float)(row - col - 1)) : 0.f;
                    __nv_bfloat16 h0,l0,h1,l1;
                    split1(v0,h0,l0); split1(v1,h1,l1);
                    *(__nv_bfloat162*)(ath + row*SATT + col) = __nv_bfloat162(h0,h1);
                    *(__nv_bfloat162*)(atl + row*SATT + col) = __nv_bfloat162(l0,l1);
                }
    }
    // v: wait staging, read to regs, convert in place
    CP_WAIT0();
    __syncthreads();
    float4 vr[8];
#pragma unroll
    for (int it = 0; it < 8; it++) vr[it] = ((const float4*)vst)[tid + it*256];
    __syncthreads();
#pragma unroll
    for (int it = 0; it < 8; it++) {
        int idx = tid + it * 256;
        int r = idx >> 5, c = (idx & 31) << 2;
        cvt4(vh, vl, r * SA + c, vr[it]);
    }
    __syncthreads();

    // ---- o_intra mma: M=64 N=128 K=64, warps 2x4 (tile 32x32), B=v^T via trans ----
    {
        float acc2[2][4][4];
#pragma unroll
        for (int mi = 0; mi < 2; mi++)
#pragma unroll
            for (int j = 0; j < 4; j++)
#pragma unroll
                for (int r = 0; r < 4; r++) acc2[mi][j][r] = 0.f;

        const int arow = wm * 32 + (lane & 15);
        const int akoff = (lane >> 4) * 8;
#pragma unroll
        for (int kk = 0; kk < 4; kk++) {
            uint32_t aah[2][4], aal[2][4], bvh[2][4], bvl[2][4];
#pragma unroll
            for (int mi = 0; mi < 2; mi++) {
                uint32_t ao = (uint32_t)(((arow + mi*16) * SATT + kk*16 + akoff) * 2);
                ldsm4(aah[mi], uath + ao);
                ldsm4(aal[mi], uatl + ao);
            }
#pragma unroll
            for (int nb = 0; nb < 2; nb++) {
                int c2 = kk*16 + (lane & 7) + ((lane >> 3) & 1) * 8;
                int e  = wn*32 + nb*16 + ((lane >> 4) & 1) * 8;
                uint32_t bo = (uint32_t)((c2 * SA + e) * 2);
                ldsm4t(bvh[nb], uvh + bo);
                ldsm4t(bvl[nb], uvl + bo);
            }
#pragma unroll
            for (int mi = 0; mi < 2; mi++)
#pragma unroll
                for (int nb = 0; nb < 2; nb++)
#pragma unroll
                    for (int ni = 0; ni < 2; ni++) {
                        mma16816(acc2[mi][nb*2+ni], aah[mi], bvh[nb][ni*2], bvh[nb][ni*2+1]);
                        mma16816(acc2[mi][nb*2+ni], aah[mi], bvl[nb][ni*2], bvl[nb][ni*2+1]);
                        mma16816(acc2[mi][nb*2+ni], aal[mi], bvh[nb][ni*2], bvh[nb][ni*2+1]);
                    }
        }
        // write o_intra
#pragma unroll
        for (int mi = 0; mi < 2; mi++)
#pragma unroll
            for (int j = 0; j < 4; j++) {
                int c = wm*32 + mi*16 + (lane >> 2);
                int e = wn*32 + (j>>1)*16 + (j&1)*8 + (lane & 3)*2;
                float* op = g_o + ((size_t)(b*TT + ch*CHK + c)) * HIDD + h*DD + e;
                *(float2*)op              = make_float2(acc2[mi][j][0], acc2[mi][j][1]);
                *(float2*)(op + 8*HIDD)   = make_float2(acc2[mi][j][2], acc2[mi][j][3]);
            }
    }
}

// =================================================================
// GLA kernel B (scan): S in mma accum regs; o += qdec * (q @ S_prev)
// grid (B*H, 4 e-tiles of 32), 256 threads.
// =================================================================
__global__ void __launch_bounds__(256)
gla_scan()
{
    extern __shared__ __nv_bfloat16 smB[];
    __nv_bfloat16 *qh = smB,          *ql = qh + 64*SA,
                  *kh = ql + 64*SA,   *kl = kh + 64*SA,
                  *vh = kl + 64*SA,   *vl = vh + 64*SV,
                  *sTh = vl + 64*SV,  *sTl = sTh + 32*SA;
    const int tid = threadIdx.x, warp = tid >> 5, lane = tid & 31;
    const int bh = blockIdx.x, b = bh >> 4, h = bh & 15;
    const int e0 = blockIdx.y * 32;
    const float g = -exp2f(-0.5f * (float)(h + 1)) * (1.0f - 11.0f/31.0f + 1e-5f);
    const float chdec = expf(g * 64.f);

    const float* qg = g_q + (size_t)bh * TT * DD;
    const float* kg = g_k + (size_t)bh * TT * DD;
    const float* vg = g_v + (size_t)bh * TT * DD;

    const uint32_t uqh = s2u(qh), uql = s2u(ql), ukh = s2u(kh), ukl = s2u(kl);
    const uint32_t uvh = s2u(vh), uvl = s2u(vl), usth = s2u(sTh), ustl = s2u(sTl);

    // S warp layout: 4x2 warps, tile 32(d) x 16(e)
    const int wmS = warp >> 1, wnS = warp & 1;
    float accS[2][2][4];
#pragma unroll
    for (int mi = 0; mi < 2; mi++)
#pragma unroll
        for (int ni = 0; ni < 2; ni++)
#pragma unroll
            for (int r = 0; r < 4; r++) accS[mi][ni][r] = 0.f;

    for (int ch = 0; ch < NCK; ch++) {
        // dump S_prev -> sT (hi/lo), then scale accS by chdec
#pragma unroll
        for (int mi = 0; mi < 2; mi++)
#pragma unroll
            for (int ni = 0; ni < 2; ni++)
#pragma unroll
                for (int r = 0; r < 4; r++) {
                    int d = wmS*32 + mi*16 + (lane >> 2) + (r >> 1)*8;
                    int e = wnS*16 + ni*8 + (lane & 3)*2 + (r & 1);
                    float val = accS[mi][ni][r];
                    __nv_bfloat16 hh, ll;
                    split1(val, hh, ll);
                    sTh[e*SA + d] = hh;
                    sTl[e*SA + d] = ll;
                    accS[mi][ni][r] = val * chdec;
                }
        // convert q, k*kdec
        const float* qrow = qg + (size_t)ch * CHK * DD;
        const float* krow = kg + (size_t)ch * CHK * DD;
        const float* vrow = vg + (size_t)ch * CHK * DD;
#pragma unroll
        for (int it = 0; it < 8; it++) {
            int idx = tid + it * 256;
            int r = idx >> 5, c = (idx & 31) << 2;
            cvt4(qh, ql, r*SA + c, *(const float4*)(qrow + r*DD + c));
            float4 kv = *(const float4*)(krow + r*DD + c);
            float kd = expf(g * (float)(63 - r));
            kv.x *= kd; kv.y *= kd; kv.z *= kd; kv.w *= kd;
            cvt4(kh, kl, r*SA + c, kv);
        }
        // v e-tile
#pragma unroll
        for (int it = 0; it < 2; it++) {
            int idx = tid + it * 256;
            int r = idx >> 3, c = (idx & 7) << 2;
            cvt4(vh, vl, r*SV + c, *(const float4*)(vrow + r*DD + e0 + c));
        }
        __syncthreads();

        // S += (k*kdec)^T @ v : M=128(d) N=32(e) K=64(c); both operands trans
#pragma unroll
        for (int kk = 0; kk < 4; kk++) {
            uint32_t akh[2][4], akl[2][4], bvh4[4], bvl4[4];
#pragma unroll
            for (int mi = 0; mi < 2; mi++) {
                int c2 = kk*16 + (lane & 7) + ((lane >> 4) & 1) * 8;
                int d  = wmS*32 + mi*16 + ((lane >> 3) & 1) * 8;
                uint32_t ao = (uint32_t)((c2 * SA + d) * 2);
                ldsm4t(akh[mi], ukh + ao);
                ldsm4t(akl[mi], ukl + ao);
            }
            {
                int c2 = kk*16 + (lane & 7) + ((lane >> 3) & 1) * 8;
                int e  = wnS*16 + ((lane >> 4) & 1) * 8;
                uint32_t bo = (uint32_t)((c2 * SV + e) * 2);
                ldsm4t(bvh4, uvh + bo);
                ldsm4t(bvl4, uvl + bo);
            }
#pragma unroll
            for (int mi = 0; mi < 2; mi++)
#pragma unroll
                for (int ni = 0; ni < 2; ni++) {
                    mma16816(accS[mi][ni], akh[mi], bvh4[ni*2], bvh4[ni*2+1]);
                    mma16816(accS[mi][ni], akh[mi], bvl4[ni*2], bvl4[ni*2+1]);
                    mma16816(accS[mi][ni], akl[mi], bvh4[ni*2], bvh4[ni*2+1]);
                }
        }

        // o_inter = q @ S_prev : M=64(c) N=32(e) K=128(d); warps 4x2, tile 16x16
        {
            float accO[2][4];
#pragma unroll
            for (int ni = 0; ni < 2; ni++)
#pragma unroll
                for (int r = 0; r < 4; r++) accO[ni][r] = 0.f;

            const int arow = wmS*16 + (lane & 15);
            const int akoff = (lane >> 4) * 8;
            const int brow = wnS*16 + (lane & 7) + ((lane >> 4) & 1) * 8;
            const int bkoff = ((lane >> 3) & 1) * 8;
#pragma unroll
            for (int kk = 0; kk < 8; kk++) {
                uint32_t aqh[4], aql[4], bsh[4], bsl[4];
                uint32_t ao = (uint32_t)((arow * SA + kk*16 + akoff) * 2);
                ldsm4(aqh, uqh + ao);
                ldsm4(aql, uql + ao);
                uint32_t bo = (uint32_t)((brow * SA + kk*16 + bkoff) * 2);
                ldsm4(bsh, usth + bo);
                ldsm4(bsl, ustl + bo);
#pragma unroll
                for (int ni = 0; ni < 2; ni++) {
                    mma16816(accO[ni], aqh, bsh[ni*2], bsh[ni*2+1]);
                    mma16816(accO[ni], aqh, bsl[ni*2], bsl[ni*2+1]);
                    mma16816(accO[ni], aql, bsh[ni*2], bsh[ni*2+1]);
                }
            }
            // RMW epilogue: g_o += qdec * o_inter
#pragma unroll
            for (int ni = 0; ni < 2; ni++) {
                int c = wmS*16 + (lane >> 2);
                int e = wnS*16 + ni*8 + (lane & 3)*2;
                float qd0 = expf(g * (float)(c + 1));
                float qd1 = expf(g * (float)(c + 9));
                float* op = g_o + ((size_t)(b*TT + ch*CHK + c)) * HIDD + h*DD + e0 + e;
                float2 cur = *(float2*)op;
                cur.x += qd0 * accO[ni][0];
                cur.y += qd0 * accO[ni][1];
                *(float2*)op = cur;
                float* op2 = op + 8*HIDD;
                float2 cur2 = *(float2*)op2;
                cur2.x += qd1 * accO[ni][2];
                cur2.y += qd1 * accO[ni][3];
                *(float2*)op2 = cur2;
            }
        }
        __syncthreads();
    }
}

// =================================================================
// group RMSNorm(o) * g_norm_w * gate -> overwrite g_gate
// =================================================================
__global__ void __launch_bounds__(128)
gate_norm_kernel(const float* __restrict__ gnw)
{
    const int blk = blockIdx.x;
    const int bt = blk >> 4, h = blk & 15;
    const int d = threadIdx.x;
    __shared__ float red[4];
    const size_t idx = (size_t)bt * HIDD + h * DD + d;
    float v = g_o[idx];
    float ss = v * v;
#pragma unroll
    for (int o = 16; o; o >>= 1) ss += __shfl_xor_sync(0xffffffffu, ss, o);
    if ((d & 31) == 0) red[d >> 5] = ss;
    __syncthreads();
    float rs = rsqrtf((red[0] + red[1] + red[2] + red[3]) * (1.f / 128.f) + 1e-6f);
    float gate = g_gate[idx];
    g_gate[idx] = gnw[h * DD + d] * v * rs * gate;
}

// =================================================================
// launch
// =================================================================
extern "C" void kernel_launch(void* const* d_in, const int* in_sizes, int n_in,
                              void* d_out, int out_size)
{
    const float* hidden   = (const float*)d_in[0];
    const float* w_qkv    = (const float*)d_in[1];
    const float* q_ln_w   = (const float*)d_in[2];
    const float* k_ln_w   = (const float*)d_in[3];
    const float* g_norm_w = (const float*)d_in[4];
    const float* w_gproj  = (const float*)d_in[5];
    const float* w_dense  = (const float*)d_in[6];
    const int*   pos      = (const int*)d_in[7];
    float* out = (float*)d_out;

    void *pqkv, *pgate, *pah, *pal, *pwqh, *pwql, *pwgh, *pwgl, *pwdh, *pwdl;
    cudaGetSymbolAddress(&pqkv, g_qkv);
    cudaGetSymbolAddress(&pgate, g_gate);
    cudaGetSymbolAddress(&pah, g_ah);
    cudaGetSymbolAddress(&pal, g_al);
    cudaGetSymbolAddress(&pwqh, g_wqh);
    cudaGetSymbolAddress(&pwql, g_wql);
    cudaGetSymbolAddress(&pwgh, g_wgh);
    cudaGetSymbolAddress(&pwgl, g_wgl);
    cudaGetSymbolAddress(&pwdh, g_wdh);
    cudaGetSymbolAddress(&pwdl, g_wdl);

    cudaFuncSetAttribute(gemm_bf16x3<0>, cudaFuncAttributeMaxDynamicSharedMemorySize, GEMM_DYN);
    cudaFuncSetAttribute(gemm_bf16x3<1>, cudaFuncAttributeMaxDynamicSharedMemorySize, GEMM_DYN);
    cudaFuncSetAttribute(gla_intra, cudaFuncAttributeMaxDynamicSharedMemorySize, GLAA_DYN);
    cudaFuncSetAttribute(gla_scan, cudaFuncAttributeMaxDynamicSharedMemorySize, GLAS_DYN);

    // 0) bf16 hi/lo conversions
    cvt_split<<<(MM*HIDD/4 + 255)/256, 256>>>(hidden, (__nv_bfloat16*)pah, (__nv_bfloat16*)pal, MM*HIDD/4);
    cvt_split<<<(NQKV*HIDD/4 + 255)/256, 256>>>(w_qkv, (__nv_bfloat16*)pwqh, (__nv_bfloat16*)pwql, NQKV*HIDD/4);
    cvt_split<<<(HIDD*HIDD/4 + 255)/256, 256>>>(w_gproj, (__nv_bfloat16*)pwgh, (__nv_bfloat16*)pwgl, HIDD*HIDD/4);
    cvt_split<<<(HIDD*HIDD/4 + 255)/256, 256>>>(w_dense, (__nv_bfloat16*)pwdh, (__nv_bfloat16*)pwdl, HIDD*HIDD/4);

    // 1) qkv = hidden @ w_qkv^T
    gemm_bf16x3<0><<<dim3(NQKV/GBN, MM/GBM), 256, GEMM_DYN>>>(
        (const __nv_bfloat16*)pah, (const __nv_bfloat16*)pal,
        (const __nv_bfloat16*)pwqh, (const __nv_bfloat16*)pwql,
        (float*)pqkv, NQKV);
    // 2) gate = sigmoid(hidden @ w_gproj^T)
    gemm_bf16x3<1><<<dim3(HIDD/GBN, MM/GBM), 256, GEMM_DYN>>>(
        (const __nv_bfloat16*)pah, (const __nv_bfloat16*)pal,
        (const __nv_bfloat16*)pwgh, (const __nv_bfloat16*)pwgl,
        (float*)pgate, HIDD);
    // 3) per-head rmsnorm + rope + layout (B,H,T,D)
    norm_rope_kernel<<<MM * HH, 128>>>(q_ln_w, k_ln_w, pos);
    // 4a) GLA intra-chunk (parallel over chunks)
    gla_intra<<<dim3(NCK, BB * HH), 256, GLAA_DYN>>>();
    // 4b) GLA state scan (sequential over chunks, S in registers)
    gla_scan<<<dim3(BB * HH, 4), 256, GLAS_DYN>>>();
    // 5) x = groupnorm(o) * w * gate
    gate_norm_kernel<<<MM * HH, 128>>>(g_norm_w);
    // 6) convert x -> bf16 hi/lo (reuse A buffers)
    cvt_split<<<(MM*HIDD/4 + 255)/256, 256>>>((const float*)pgate,
        (__nv_bfloat16*)pah, (__nv_bfloat16*)pal, MM*HIDD/4);
    // 7) out = x @ w_dense^T
    gemm_bf16x3<0><<<dim3(HIDD/GBN, MM/GBM), 256, GEMM_DYN>>>(
        (const __nv_bfloat16*)pah, (const __nv_bfloat16*)pal,
        (const __nv_bfloat16*)pwdh, (const __nv_bfloat16*)pwdl,
        out, HIDD);
}

// round 7
// speedup vs baseline: 3.0581x; 1.1615x over previous
#include <cuda_runtime.h>
#include <cuda_bf16.h>
#include <math.h>
#include <stdint.h>

// ---------------- problem constants ----------------
#define BB   2
#define TT   4096
#define HIDD 2048
#define HH   16
#define DD   128
#define MM   (BB*TT)          // 8192
#define NQKV (3*HIDD)         // 6144
#define CHK  64
#define NCK  (TT/CHK)         // 64

// ---------------- GEMM tiling (HMMA mma.sync path) ----------------
#define GBM 128
#define GBN 128
#define GBK 32
#define NKI (HIDD/GBK)            // 64
#define TPAD 40                   // padded row stride in halfs
#define TILE_B (GBM*TPAD*2)       // 10240 bytes per operand tile
#define OFF_AH 0
#define OFF_AL (1*TILE_B)
#define OFF_BH (2*TILE_B)
#define OFF_BL (3*TILE_B)
#define STAGE_B (4*TILE_B)        // 40960
#define NSTAGE 2
#define GEMM_DYN (NSTAGE*STAGE_B) // 81920  -> 2 CTAs/SM

// ---------------- GLA tiling ----------------
#define SA   136                  // q/k/v tile stride (halfs)
#define SATT 72                   // att tile stride
#define SV   40                   // v e-tile stride (scan kernel)
#define GLAA_HALFS (6*64*SA + 2*64*SATT)              // 61440
#define GLAA_DYN   (GLAA_HALFS*2)                     // 122880
#define GLAS_HALFS (4*64*SA + 2*64*SV + 2*32*SA)      // 48640
#define GLAS_DYN   (GLAS_HALFS*2)                     // 97280

// ---------------- scratch (static device memory) ----------------
__device__ float g_qkv [(size_t)MM*NQKV];
__device__ float g_q   [(size_t)BB*HH*TT*DD];
__device__ float g_k   [(size_t)BB*HH*TT*DD];
__device__ float g_v   [(size_t)BB*HH*TT*DD];
__device__ float g_o   [(size_t)MM*HIDD];
__device__ float g_gate[(size_t)MM*HIDD];
__device__ __nv_bfloat16 g_ah [(size_t)MM*HIDD];
__device__ __nv_bfloat16 g_al [(size_t)MM*HIDD];
__device__ __nv_bfloat16 g_wqh[(size_t)NQKV*HIDD];
__device__ __nv_bfloat16 g_wql[(size_t)NQKV*HIDD];
__device__ __nv_bfloat16 g_wgh[(size_t)HIDD*HIDD];
__device__ __nv_bfloat16 g_wgl[(size_t)HIDD*HIDD];
__device__ __nv_bfloat16 g_wdh[(size_t)HIDD*HIDD];
__device__ __nv_bfloat16 g_wdl[(size_t)HIDD*HIDD];

// ---------------- ptx helpers ----------------
__device__ __forceinline__ uint32_t s2u(const void* p) {
    uint32_t a;
    asm("{ .reg .u64 t; cvta.to.shared.u64 t, %1; cvt.u32.u64 %0, t; }"
        : "=r"(a) : "l"(p));
    return a;
}
__device__ __forceinline__ void cpa16(uint32_t dst, const void* src) {
    asm volatile("cp.async.cg.shared.global [%0], [%1], 16;" :: "r"(dst), "l"(src));
}
#define CP_COMMIT() asm volatile("cp.async.commit_group;" ::: "memory")
#define CP_WAIT1()  asm volatile("cp.async.wait_group 1;" ::: "memory")
#define CP_WAIT0()  asm volatile("cp.async.wait_group 0;" ::: "memory")

__device__ __forceinline__ void ldsm4(uint32_t (&r)[4], uint32_t addr) {
    asm volatile("ldmatrix.sync.aligned.m8n8.x4.shared.b16 {%0,%1,%2,%3}, [%4];"
        : "=r"(r[0]), "=r"(r[1]), "=r"(r[2]), "=r"(r[3]) : "r"(addr));
}
__device__ __forceinline__ void ldsm4t(uint32_t (&r)[4], uint32_t addr) {
    asm volatile("ldmatrix.sync.aligned.m8n8.x4.trans.shared.b16 {%0,%1,%2,%3}, [%4];"
        : "=r"(r[0]), "=r"(r[1]), "=r"(r[2]), "=r"(r[3]) : "r"(addr));
}
__device__ __forceinline__ void mma16816(float (&d)[4], const uint32_t (&a)[4],
                                         uint32_t b0, uint32_t b1) {
    asm volatile(
        "mma.sync.aligned.m16n8k16.row.col.f32.bf16.bf16.f32 "
        "{%0,%1,%2,%3}, {%4,%5,%6,%7}, {%8,%9}, {%0,%1,%2,%3};"
        : "+f"(d[0]), "+f"(d[1]), "+f"(d[2]), "+f"(d[3])
        : "r"(a[0]), "r"(a[1]), "r"(a[2]), "r"(a[3]), "r"(b0), "r"(b1));
}

__device__ __forceinline__ void split1(float v, __nv_bfloat16& h, __nv_bfloat16& l) {
    h = __float2bfloat16_rn(v);
    l = __float2bfloat16_rn(v - __bfloat162float(h));
}
__device__ __forceinline__ void cvt4(__nv_bfloat16* H, __nv_bfloat16* L, int off, float4 v) {
    __nv_bfloat16 h0,l0,h1,l1,h2,l2,h3,l3;
    split1(v.x,h0,l0); split1(v.y,h1,l1); split1(v.z,h2,l2); split1(v.w,h3,l3);
    *(__nv_bfloat162*)(H+off)   = __nv_bfloat162(h0,h1);
    *(__nv_bfloat162*)(H+off+2) = __nv_bfloat162(h2,h3);
    *(__nv_bfloat162*)(L+off)   = __nv_bfloat162(l0,l1);
    *(__nv_bfloat162*)(L+off+2) = __nv_bfloat162(l2,l3);
}

// =================================================================
// split fp32 -> (bf16 hi, bf16 lo)
// =================================================================
__global__ void __launch_bounds__(256)
cvt_split(const float* __restrict__ x, __nv_bfloat16* __restrict__ hi,
          __nv_bfloat16* __restrict__ lo, int n4)
{
    int i = blockIdx.x * 256 + threadIdx.x;
    if (i >= n4) return;
    float4 v = ((const float4*)x)[i];
    __nv_bfloat16 h0,l0,h1,l1,h2,l2,h3,l3;
    split1(v.x,h0,l0); split1(v.y,h1,l1); split1(v.z,h2,l2); split1(v.w,h3,l3);
    ((__nv_bfloat162*)hi)[2*i]   = __nv_bfloat162(h0, h1);
    ((__nv_bfloat162*)hi)[2*i+1] = __nv_bfloat162(h2, h3);
    ((__nv_bfloat162*)lo)[2*i]   = __nv_bfloat162(l0, l1);
    ((__nv_bfloat162*)lo)[2*i+1] = __nv_bfloat162(l2, l3);
}

// =================================================================
// bf16x3 GEMM via mma.sync (TN): 2-stage pipeline, 2 CTAs/SM target
// =================================================================
template<int MODE>
__global__ void __launch_bounds__(256, 2)
gemm_bf16x3(const __nv_bfloat16* __restrict__ Ah, const __nv_bfloat16* __restrict__ Al,
            const __nv_bfloat16* __restrict__ Bh, const __nv_bfloat16* __restrict__ Bl,
            float* __restrict__ C, int Nn)
{
    extern __shared__ char dyn[];
    const uint32_t sb = s2u(dyn);
    const int tid = threadIdx.x;
    const int warp = tid >> 5, lane = tid & 31;
    const int wm = warp >> 2, wn = warp & 3;
    const int bm = blockIdx.y * GBM, bn = blockIdx.x * GBN;

    const __nv_bfloat16* apH = Ah + (size_t)bm * HIDD;
    const __nv_bfloat16* apL = Al + (size_t)bm * HIDD;
    const __nv_bfloat16* bpH = Bh + (size_t)bn * HIDD;
    const __nv_bfloat16* bpL = Bl + (size_t)bn * HIDD;

    float acc[4][4][4];
#pragma unroll
    for (int mi = 0; mi < 4; mi++)
#pragma unroll
        for (int ni = 0; ni < 4; ni++)
#pragma unroll
            for (int r = 0; r < 4; r++) acc[mi][ni][r] = 0.f;

    const int a_row = wm * 64 + (lane & 7) + ((lane >> 3) & 1) * 8;
    const int a_koff = (lane >> 4) * 8;
    const int b_row = wn * 32 + (lane & 7) + ((lane >> 4) & 1) * 8;
    const int b_koff = ((lane >> 3) & 1) * 8;

    auto fill = [&](int s, int k0) {
        const uint32_t base = sb + s * STAGE_B;
#pragma unroll
        for (int it = 0; it < 2; it++) {
            const int idx = tid + it * 256;
            const int row = idx >> 2;
            const int ch = idx & 3;
            const uint32_t d = (uint32_t)(row * (TPAD * 2) + ch * 16);
            const size_t gsrc = (size_t)row * HIDD + k0 + ch * 8;
            cpa16(base + OFF_AH + d, apH + gsrc);
            cpa16(base + OFF_AL + d, apL + gsrc);
            cpa16(base + OFF_BH + d, bpH + gsrc);
            cpa16(base + OFF_BL + d, bpL + gsrc);
        }
    };

    fill(0, 0);
    CP_COMMIT();

    for (int i = 0; i < NKI; i++) {
        const int s = i & 1;
        if (i + 1 < NKI) {
            fill(s ^ 1, (i + 1) * GBK);
            CP_COMMIT();
            CP_WAIT1();
        } else {
            CP_WAIT0();
        }
        __syncthreads();

        const uint32_t st = sb + s * STAGE_B;
#pragma unroll
        for (int ks = 0; ks < 2; ks++) {
            uint32_t ah[4][4], al[4][4], bb[2][4];
#pragma unroll
            for (int mi = 0; mi < 4; mi++) {
                const uint32_t ao = (uint32_t)(((a_row + mi * 16) * TPAD + ks * 16 + a_koff) * 2);
                ldsm4(ah[mi], st + OFF_AH + ao);
                ldsm4(al[mi], st + OFF_AL + ao);
            }
#pragma unroll
            for (int nb = 0; nb < 2; nb++) {
                const uint32_t bo = (uint32_t)(((b_row + nb * 16) * TPAD + ks * 16 + b_koff) * 2);
                ldsm4(bb[nb], st + OFF_BH + bo);
            }
#pragma unroll
            for (int mi = 0; mi < 4; mi++)
#pragma unroll
                for (int ni = 0; ni < 4; ni++)
                    mma16816(acc[mi][ni], ah[mi], bb[ni >> 1][(ni & 1) * 2], bb[ni >> 1][(ni & 1) * 2 + 1]);
#pragma unroll
            for (int mi = 0; mi < 4; mi++)
#pragma unroll
                for (int ni = 0; ni < 4; ni++)
                    mma16816(acc[mi][ni], al[mi], bb[ni >> 1][(ni & 1) * 2], bb[ni >> 1][(ni & 1) * 2 + 1]);
#pragma unroll
            for (int nb = 0; nb < 2; nb++) {
                const uint32_t bo = (uint32_t)(((b_row + nb * 16) * TPAD + ks * 16 + b_koff) * 2);
                ldsm4(bb[nb], st + OFF_BL + bo);
            }
#pragma unroll
            for (int mi = 0; mi < 4; mi++)
#pragma unroll
                for (int ni = 0; ni < 4; ni++)
                    mma16816(acc[mi][ni], ah[mi], bb[ni >> 1][(ni & 1) * 2], bb[ni >> 1][(ni & 1) * 2 + 1]);
        }
        __syncthreads();
    }

    const int r0 = bm + wm * 64 + (lane >> 2);
    const int c0 = bn + wn * 32 + (lane & 3) * 2;
#pragma unroll
    for (int mi = 0; mi < 4; mi++) {
#pragma unroll
        for (int ni = 0; ni < 4; ni++) {
            float2 v0 = make_float2(acc[mi][ni][0], acc[mi][ni][1]);
            float2 v1 = make_float2(acc[mi][ni][2], acc[mi][ni][3]);
            if (MODE == 1) {
                v0.x = 1.f / (1.f + __expf(-v0.x));
                v0.y = 1.f / (1.f + __expf(-v0.y));
                v1.x = 1.f / (1.f + __expf(-v1.x));
                v1.y = 1.f / (1.f + __expf(-v1.y));
            }
            *(float2*)(C + (size_t)(r0 + mi * 16) * Nn + c0 + ni * 8) = v0;
            *(float2*)(C + (size_t)(r0 + mi * 16 + 8) * Nn + c0 + ni * 8) = v1;
        }
    }
}

// =================================================================
// Per-head RMSNorm + RoPE + transpose to (B,H,T,D) — unchanged
// =================================================================
__global__ void __launch_bounds__(128)
norm_rope_kernel(const float* __restrict__ qw, const float* __restrict__ kw,
                 const int* __restrict__ pos)
{
    const int blk = blockIdx.x;
    const int bt = blk >> 4, h = blk & 15;
    const int b = bt >> 12, t = bt & 4095;
    const int d = threadIdx.x;
    __shared__ float buf[128];
    __shared__ float red[4];

    const float* base = g_qkv + (size_t)bt * NQKV + h * DD;
    const int p = pos[bt];

    float cth = 1.f, sth = 0.f;
    if (d < 64) {
        int i = d & 31;
        float freq = (float)p * powf(10000.f, -(float)(2 * i) / 64.f);
        cth = cosf(freq); sth = sinf(freq);
    }
    const size_t oidx = ((size_t)(b * HH + h) * TT + t) * DD + d;

    {
        float v = base[d];
        float ss = v * v;
#pragma unroll
        for (int o = 16; o; o >>= 1) ss += __shfl_xor_sync(0xffffffffu, ss, o);
        if ((d & 31) == 0) red[d >> 5] = ss;
        __syncthreads();
        float rs = rsqrtf((red[0] + red[1] + red[2] + red[3]) * (1.f / 128.f) + 1e-6f);
        float nv = qw[d] * v * rs;
        buf[d] = nv;
        __syncthreads();
        float o = nv;
        if (d < 64) {
            float partner = (d < 32) ? -buf[d + 32] : buf[d - 32];
            o = nv * cth + partner * sth;
        }
        g_q[oidx] = o * 0.08838834764831845f;
        __syncthreads();
    }
    {
        float v = base[HIDD + d];
        float ss = v * v;
#pragma unroll
        for (int o = 16; o; o >>= 1) ss += __shfl_xor_sync(0xffffffffu, ss, o);
        if ((d & 31) == 0) red[d >> 5] = ss;
        __syncthreads();
        float rs = rsqrtf((red[0] + red[1] + red[2] + red[3]) * (1.f / 128.f) + 1e-6f);
        float nv = kw[d] * v * rs;
        buf[d] = nv;
        __syncthreads();
        float o = nv;
        if (d < 64) {
            float partner = (d < 32) ? -buf[d + 32] : buf[d - 32];
            o = nv * cth + partner * sth;
        }
        g_k[oidx] = o;
    }
    g_v[oidx] = base[2 * HIDD + d];
}

// =================================================================
// GLA kernel A (parallel): att = (q@k^T)*mask ; o_intra = att@v
// =================================================================
__global__ void __launch_bounds__(256)
gla_intra()
{
    extern __shared__ __nv_bfloat16 smA[];
    __nv_bfloat16 *qh = smA,           *ql = qh + 64*SA,
                  *kh = ql + 64*SA,    *kl = kh + 64*SA,
                  *vh = kl + 64*SA,    *vl = vh + 64*SA,
                  *ath = vl + 64*SA,   *atl = ath + 64*SATT;
    const int tid = threadIdx.x, warp = tid >> 5, lane = tid & 31;
    const int ch = blockIdx.x, bh = blockIdx.y, b = bh >> 4, h = bh & 15;
    const float g = -exp2f(-0.5f * (float)(h + 1)) * (1.0f - 11.0f/31.0f + 1e-5f);

    const float* qg = g_q + ((size_t)bh * TT + ch * CHK) * DD;
    const float* kg = g_k + ((size_t)bh * TT + ch * CHK) * DD;
    const float* vg = g_v + ((size_t)bh * TT + ch * CHK) * DD;

    const uint32_t uqh = s2u(qh), uql = s2u(ql), ukh = s2u(kh), ukl = s2u(kl);
    const uint32_t uvh = s2u(vh), uvl = s2u(vl), uath = s2u(ath), uatl = s2u(atl);

    const uint32_t uvst = uvh;
    float* vst = (float*)vh;
#pragma unroll
    for (int it = 0; it < 8; it++) {
        int idx = tid + it * 256;
        cpa16(uvst + idx * 16, vg + idx * 4);
    }
    CP_COMMIT();

#pragma unroll
    for (int it = 0; it < 8; it++) {
        int idx = tid + it * 256;
        int r = idx >> 5, c = (idx & 31) << 2;
        cvt4(qh, ql, r * SA + c, *(const float4*)(qg + r * DD + c));
        cvt4(kh, kl, r * SA + c, *(const float4*)(kg + r * DD + c));
    }
    __syncthreads();

    const int wm = warp >> 2, wn = warp & 3;
    {
        float acc[2][2][4];
#pragma unroll
        for (int mi = 0; mi < 2; mi++)
#pragma unroll
            for (int ni = 0; ni < 2; ni++)
#pragma unroll
                for (int r = 0; r < 4; r++) acc[mi][ni][r] = 0.f;

        const int arow = wm * 32 + (lane & 15);
        const int akoff = (lane >> 4) * 8;
        const int brow = wn * 16 + (lane & 7) + ((lane >> 4) & 1) * 8;
        const int bkoff = ((lane >> 3) & 1) * 8;
#pragma unroll
        for (int kk = 0; kk < 8; kk++) {
            uint32_t ahh[2][4], all[2][4], bhf[4], blf[4];
#pragma unroll
            for (int mi = 0; mi < 2; mi++) {
                uint32_t ao = (uint32_t)(((arow + mi*16) * SA + kk*16 + akoff) * 2);
                ldsm4(ahh[mi], uqh + ao);
                ldsm4(all[mi], uql + ao);
            }
            uint32_t bo = (uint32_t)((brow * SA + kk*16 + bkoff) * 2);
            ldsm4(bhf, ukh + bo);
            ldsm4(blf, ukl + bo);
#pragma unroll
            for (int mi = 0; mi < 2; mi++)
#pragma unroll
                for (int ni = 0; ni < 2; ni++) {
                    mma16816(acc[mi][ni], ahh[mi], bhf[ni*2], bhf[ni*2+1]);
                    mma16816(acc[mi][ni], ahh[mi], blf[ni*2], blf[ni*2+1]);
                    mma16816(acc[mi][ni], all[mi], bhf[ni*2], bhf[ni*2+1]);
                }
        }
#pragma unroll
        for (int mi = 0; mi < 2; mi++)
#pragma unroll
            for (int ni = 0; ni < 2; ni++)
#pragma unroll
                for (int half = 0; half < 2; half++) {
                    int row = wm*32 + mi*16 + (lane >> 2) + half*8;
                    int col = wn*16 + ni*8 + (lane & 3)*2;
                    float v0 = acc[mi][ni][half*2+0];
                    float v1 = acc[mi][ni][half*2+1];
                    v0 = (row >= col)     ? v0 * __expf(g * (float)(row - col))     : 0.f;
                    v1 = (row >= col + 1) ? v1 * __expf(g * (float)(row - col - 1)) : 0.f;
                    __nv_bfloat16 h0,l0,h1,l1;
                    split1(v0,h0,l0); split1(v1,h1,l1);
                    *(__nv_bfloat162*)(ath + row*SATT + col) = __nv_bfloat162(h0,h1);
                    *(__nv_bfloat162*)(atl + row*SATT + col) = __nv_bfloat162(l0,l1);
                }
    }
    CP_WAIT0();
    __syncthreads();
    float4 vr[8];
#pragma unroll
    for (int it = 0; it < 8; it++) vr[it] = ((const float4*)vst)[tid + it*256];
    __syncthreads();
#pragma unroll
    for (int it = 0; it < 8; it++) {
        int idx = tid + it * 256;
        int r = idx >> 5, c = (idx & 31) << 2;
        cvt4(vh, vl, r * SA + c, vr[it]);
    }
    __syncthreads();

    {
        float acc2[2][4][4];
#pragma unroll
        for (int mi = 0; mi < 2; mi++)
#pragma unroll
            for (int j = 0; j < 4; j++)
#pragma unroll
                for (int r = 0; r < 4; r++) acc2[mi][j][r] = 0.f;

        const int arow = wm * 32 + (lane & 15);
        const int akoff = (lane >> 4) * 8;
#pragma unroll
        for (int kk = 0; kk < 4; kk++) {
            uint32_t aah[2][4], aal[2][4], bvh[2][4], bvl[2][4];
#pragma unroll
            for (int mi = 0; mi < 2; mi++) {
                uint32_t ao = (uint32_t)(((arow + mi*16) * SATT + kk*16 + akoff) * 2);
                ldsm4(aah[mi], uath + ao);
                ldsm4(aal[mi], uatl + ao);
            }
#pragma unroll
            for (int nb = 0; nb < 2; nb++) {
                int c2 = kk*16 + (lane & 7) + ((lane >> 3) & 1) * 8;
                int e  = wn*32 + nb*16 + ((lane >> 4) & 1) * 8;
                uint32_t bo = (uint32_t)((c2 * SA + e) * 2);
                ldsm4t(bvh[nb], uvh + bo);
                ldsm4t(bvl[nb], uvl + bo);
            }
#pragma unroll
            for (int mi = 0; mi < 2; mi++)
#pragma unroll
                for (int nb = 0; nb < 2; nb++)
#pragma unroll
                    for (int ni = 0; ni < 2; ni++) {
                        mma16816(acc2[mi][nb*2+ni], aah[mi], bvh[nb][ni*2], bvh[nb][ni*2+1]);
                        mma16816(acc2[mi][nb*2+ni], aah[mi], bvl[nb][ni*2], bvl[nb][ni*2+1]);
                        mma16816(acc2[mi][nb*2+ni], aal[mi], bvh[nb][ni*2], bvh[nb][ni*2+1]);
                    }
        }
#pragma unroll
        for (int mi = 0; mi < 2; mi++)
#pragma unroll
            for (int j = 0; j < 4; j++) {
                int c = wm*32 + mi*16 + (lane >> 2);
                int e = wn*32 + (j>>1)*16 + (j&1)*8 + (lane & 3)*2;
                float* op = g_o + ((size_t)(b*TT + ch*CHK + c)) * HIDD + h*DD + e;
                *(float2*)op              = make_float2(acc2[mi][j][0], acc2[mi][j][1]);
                *(float2*)(op + 8*HIDD)   = make_float2(acc2[mi][j][2], acc2[mi][j][3]);
            }
    }
}

// =================================================================
// GLA kernel B (scan): S in mma accum regs; o += qdec * (q @ S_prev)
// =================================================================
__global__ void __launch_bounds__(256)
gla_scan()
{
    extern __shared__ __nv_bfloat16 smB[];
    __nv_bfloat16 *qh = smB,          *ql = qh + 64*SA,
                  *kh = ql + 64*SA,   *kl = kh + 64*SA,
                  *vh = kl + 64*SA,   *vl = vh + 64*SV,
                  *sTh = vl + 64*SV,  *sTl = sTh + 32*SA;
    const int tid = threadIdx.x, warp = tid >> 5, lane = tid & 31;
    const int bh = blockIdx.x, b = bh >> 4, h = bh & 15;
    const int e0 = blockIdx.y * 32;
    const float g = -exp2f(-0.5f * (float)(h + 1)) * (1.0f - 11.0f/31.0f + 1e-5f);
    const float chdec = __expf(g * 64.f);

    const float* qg = g_q + (size_t)bh * TT * DD;
    const float* kg = g_k + (size_t)bh * TT * DD;
    const float* vg = g_v + (size_t)bh * TT * DD;

    const uint32_t uqh = s2u(qh), uql = s2u(ql), ukh = s2u(kh), ukl = s2u(kl);
    const uint32_t uvh = s2u(vh), uvl = s2u(vl), usth = s2u(sTh), ustl = s2u(sTl);

    const int wmS = warp >> 1, wnS = warp & 1;
    float accS[2][2][4];
#pragma unroll
    for (int mi = 0; mi < 2; mi++)
#pragma unroll
        for (int ni = 0; ni < 2; ni++)
#pragma unroll
            for (int r = 0; r < 4; r++) accS[mi][ni][r] = 0.f;

    for (int ch = 0; ch < NCK; ch++) {
#pragma unroll
        for (int mi = 0; mi < 2; mi++)
#pragma unroll
            for (int ni = 0; ni < 2; ni++)
#pragma unroll
                for (int r = 0; r < 4; r++) {
                    int d = wmS*32 + mi*16 + (lane >> 2) + (r >> 1)*8;
                    int e = wnS*16 + ni*8 + (lane & 3)*2 + (r & 1);
                    float val = accS[mi][ni][r];
                    __nv_bfloat16 hh, ll;
                    split1(val, hh, ll);
                    sTh[e*SA + d] = hh;
                    sTl[e*SA + d] = ll;
                    accS[mi][ni][r] = val * chdec;
                }
        const float* qrow = qg + (size_t)ch * CHK * DD;
        const float* krow = kg + (size_t)ch * CHK * DD;
        const float* vrow = vg + (size_t)ch * CHK * DD;
#pragma unroll
        for (int it = 0; it < 8; it++) {
            int idx = tid + it * 256;
            int r = idx >> 5, c = (idx & 31) << 2;
            cvt4(qh, ql, r*SA + c, *(const float4*)(qrow + r*DD + c));
            float4 kv = *(const float4*)(krow + r*DD + c);
            float kd = __expf(g * (float)(63 - r));
            kv.x *= kd; kv.y *= kd; kv.z *= kd; kv.w *= kd;
            cvt4(kh, kl, r*SA + c, kv);
        }
#pragma unroll
        for (int it = 0; it < 2; it++) {
            int idx = tid + it * 256;
            int r = idx >> 3, c = (idx & 7) << 2;
            cvt4(vh, vl, r*SV + c, *(const float4*)(vrow + r*DD + e0 + c));
        }
        __syncthreads();

#pragma unroll
        for (int kk = 0; kk < 4; kk++) {
            uint32_t akh[2][4], akl[2][4], bvh4[4], bvl4[4];
#pragma unroll
            for (int mi = 0; mi < 2; mi++) {
                int c2 = kk*16 + (lane & 7) + ((lane >> 4) & 1) * 8;
                int d  = wmS*32 + mi*16 + ((lane >> 3) & 1) * 8;
                uint32_t ao = (uint32_t)((c2 * SA + d) * 2);
                ldsm4t(akh[mi], ukh + ao);
                ldsm4t(akl[mi], ukl + ao);
            }
            {
                int c2 = kk*16 + (lane & 7) + ((lane >> 3) & 1) * 8;
                int e  = wnS*16 + ((lane >> 4) & 1) * 8;
                uint32_t bo = (uint32_t)((c2 * SV + e) * 2);
                ldsm4t(bvh4, uvh + bo);
                ldsm4t(bvl4, uvl + bo);
            }
#pragma unroll
            for (int mi = 0; mi < 2; mi++)
#pragma unroll
                for (int ni = 0; ni < 2; ni++) {
                    mma16816(accS[mi][ni], akh[mi], bvh4[ni*2], bvh4[ni*2+1]);
                    mma16816(accS[mi][ni], akh[mi], bvl4[ni*2], bvl4[ni*2+1]);
                    mma16816(accS[mi][ni], akl[mi], bvh4[ni*2], bvh4[ni*2+1]);
                }
        }

        {
            float accO[2][4];
#pragma unroll
            for (int ni = 0; ni < 2; ni++)
#pragma unroll
                for (int r = 0; r < 4; r++) accO[ni][r] = 0.f;

            const int arow = wmS*16 + (lane & 15);
            const int akoff = (lane >> 4) * 8;
            const int brow = wnS*16 + (lane & 7) + ((lane >> 4) & 1) * 8;
            const int bkoff = ((lane >> 3) & 1) * 8;
#pragma unroll
            for (int kk = 0; kk < 8; kk++) {
                uint32_t aqh[4], aql[4], bsh[4], bsl[4];
                uint32_t ao = (uint32_t)((arow * SA + kk*16 + akoff) * 2);
                ldsm4(aqh, uqh + ao);
                ldsm4(aql, uql + ao);
                uint32_t bo = (uint32_t)((brow * SA + kk*16 + bkoff) * 2);
                ldsm4(bsh, usth + bo);
                ldsm4(bsl, ustl + bo);
#pragma unroll
                for (int ni = 0; ni < 2; ni++) {
                    mma16816(accO[ni], aqh, bsh[ni*2], bsh[ni*2+1]);
                    mma16816(accO[ni], aqh, bsl[ni*2], bsl[ni*2+1]);
                    mma16816(accO[ni], aql, bsh[ni*2], bsh[ni*2+1]);
                }
            }
#pragma unroll
            for (int ni = 0; ni < 2; ni++) {
                int c = wmS*16 + (lane >> 2);
                int e = wnS*16 + ni*8 + (lane & 3)*2;
                float qd0 = __expf(g * (float)(c + 1));
                float qd1 = __expf(g * (float)(c + 9));
                float* op = g_o + ((size_t)(b*TT + ch*CHK + c)) * HIDD + h*DD + e0 + e;
                float2 cur = *(float2*)op;
                cur.x += qd0 * accO[ni][0];
                cur.y += qd0 * accO[ni][1];
                *(float2*)op = cur;
                float* op2 = op + 8*HIDD;
                float2 cur2 = *(float2*)op2;
                cur2.x += qd1 * accO[ni][2];
                cur2.y += qd1 * accO[ni][3];
                *(float2*)op2 = cur2;
            }
        }
        __syncthreads();
    }
}

// =================================================================
// group RMSNorm(o) * g_norm_w * gate -> write bf16 hi/lo directly
// =================================================================
__global__ void __launch_bounds__(128)
gate_norm_kernel(const float* __restrict__ gnw,
                 __nv_bfloat16* __restrict__ xh, __nv_bfloat16* __restrict__ xl)
{
    const int blk = blockIdx.x;
    const int bt = blk >> 4, h = blk & 15;
    const int d = threadIdx.x;
    __shared__ float red[4];
    const size_t idx = (size_t)bt * HIDD + h * DD + d;
    float v = g_o[idx];
    float ss = v * v;
#pragma unroll
    for (int o = 16; o; o >>= 1) ss += __shfl_xor_sync(0xffffffffu, ss, o);
    if ((d & 31) == 0) red[d >> 5] = ss;
    __syncthreads();
    float rs = rsqrtf((red[0] + red[1] + red[2] + red[3]) * (1.f / 128.f) + 1e-6f);
    float gate = g_gate[idx];
    float x = gnw[h * DD + d] * v * rs * gate;
    __nv_bfloat16 hh, ll;
    split1(x, hh, ll);
    xh[idx] = hh;
    xl[idx] = ll;
}

// =================================================================
// launch
// =================================================================
extern "C" void kernel_launch(void* const* d_in, const int* in_sizes, int n_in,
                              void* d_out, int out_size)
{
    const float* hidden   = (const float*)d_in[0];
    const float* w_qkv    = (const float*)d_in[1];
    const float* q_ln_w   = (const float*)d_in[2];
    const float* k_ln_w   = (const float*)d_in[3];
    const float* g_norm_w = (const float*)d_in[4];
    const float* w_gproj  = (const float*)d_in[5];
    const float* w_dense  = (const float*)d_in[6];
    const int*   pos      = (const int*)d_in[7];
    float* out = (float*)d_out;

    void *pqkv, *pgate, *pah, *pal, *pwqh, *pwql, *pwgh, *pwgl, *pwdh, *pwdl;
    cudaGetSymbolAddress(&pqkv, g_qkv);
    cudaGetSymbolAddress(&pgate, g_gate);
    cudaGetSymbolAddress(&pah, g_ah);
    cudaGetSymbolAddress(&pal, g_al);
    cudaGetSymbolAddress(&pwqh, g_wqh);
    cudaGetSymbolAddress(&pwql, g_wql);
    cudaGetSymbolAddress(&pwgh, g_wgh);
    cudaGetSymbolAddress(&pwgl, g_wgl);
    cudaGetSymbolAddress(&pwdh, g_wdh);
    cudaGetSymbolAddress(&pwdl, g_wdl);

    cudaFuncSetAttribute(gemm_bf16x3<0>, cudaFuncAttributeMaxDynamicSharedMemorySize, GEMM_DYN);
    cudaFuncSetAttribute(gemm_bf16x3<1>, cudaFuncAttributeMaxDynamicSharedMemorySize, GEMM_DYN);
    cudaFuncSetAttribute(gla_intra, cudaFuncAttributeMaxDynamicSharedMemorySize, GLAA_DYN);
    cudaFuncSetAttribute(gla_scan, cudaFuncAttributeMaxDynamicSharedMemorySize, GLAS_DYN);

    // 0) bf16 hi/lo conversions
    cvt_split<<<(MM*HIDD/4 + 255)/256, 256>>>(hidden, (__nv_bfloat16*)pah, (__nv_bfloat16*)pal, MM*HIDD/4);
    cvt_split<<<(NQKV*HIDD/4 + 255)/256, 256>>>(w_qkv, (__nv_bfloat16*)pwqh, (__nv_bfloat16*)pwql, NQKV*HIDD/4);
    cvt_split<<<(HIDD*HIDD/4 + 255)/256, 256>>>(w_gproj, (__nv_bfloat16*)pwgh, (__nv_bfloat16*)pwgl, HIDD*HIDD/4);
    cvt_split<<<(HIDD*HIDD/4 + 255)/256, 256>>>(w_dense, (__nv_bfloat16*)pwdh, (__nv_bfloat16*)pwdl, HIDD*HIDD/4);

    // 1) qkv = hidden @ w_qkv^T
    gemm_bf16x3<0><<<dim3(NQKV/GBN, MM/GBM), 256, GEMM_DYN>>>(
        (const __nv_bfloat16*)pah, (const __nv_bfloat16*)pal,
        (const __nv_bfloat16*)pwqh, (const __nv_bfloat16*)pwql,
        (float*)pqkv, NQKV);
    // 2) gate = sigmoid(hidden @ w_gproj^T)
    gemm_bf16x3<1><<<dim3(HIDD/GBN, MM/GBM), 256, GEMM_DYN>>>(
        (const __nv_bfloat16*)pah, (const __nv_bfloat16*)pal,
        (const __nv_bfloat16*)pwgh, (const __nv_bfloat16*)pwgl,
        (float*)pgate, HIDD);
    // 3) per-head rmsnorm + rope + layout (B,H,T,D)
    norm_rope_kernel<<<MM * HH, 128>>>(q_ln_w, k_ln_w, pos);
    // 4a) GLA intra-chunk (parallel over chunks)
    gla_intra<<<dim3(NCK, BB * HH), 256, GLAA_DYN>>>();
    // 4b) GLA state scan (sequential over chunks, S in registers)
    gla_scan<<<dim3(BB * HH, 4), 256, GLAS_DYN>>>();
    // 5) x = groupnorm(o) * w * gate -> bf16 hi/lo directly
    gate_norm_kernel<<<MM * HH, 128>>>(g_norm_w, (__nv_bfloat16*)pah, (__nv_bfloat16*)pal);
    // 6) out = x @ w_dense^T
    gemm_bf16x3<0><<<dim3(HIDD/GBN, MM/GBM), 256, GEMM_DYN>>>(
        (const __nv_bfloat16*)pah, (const __nv_bfloat16*)pal,
        (const __nv_bfloat16*)pwdh, (const __nv_bfloat16*)pwdl,
        out, HIDD);
}